// round 1
// baseline (speedup 1.0000x reference)
#include <cuda_runtime.h>

#define BB 512
#define CC 112
#define DD 128
#define HH 8
#define HDIM 16
#define KW 8
#define MM (BB*CC)   // 57344

// Scratch (allocation-free contract: __device__ globals)
__device__ float g_src[(size_t)MM * DD];           // conv+residual result
__device__ float g_q[(size_t)BB * HH * CC * HDIM]; // [B,H,S,hd]
__device__ float g_k[(size_t)BB * HH * CC * HDIM];
__device__ float g_v[(size_t)BB * HH * CC * HDIM];
__device__ float g_attn[(size_t)MM * DD];          // attention output, [B,S,D]

// ---------------------------------------------------------------------------
// Kernel 1: depthwise conv1d (pad 3,4) -> GELU(exact) -> BatchNorm(eval) ->
//           residual add with x. One block per (b,c) row of length D=128.
// ---------------------------------------------------------------------------
__global__ void k_conv(const float* __restrict__ x,
                       const float* __restrict__ cw, const float* __restrict__ cb,
                       const float* __restrict__ bg, const float* __restrict__ bbias,
                       const float* __restrict__ bm, const float* __restrict__ bvv) {
    int row = blockIdx.x;           // b*C + c
    int c = row % CC;
    __shared__ float xs[DD];
    int d = threadIdx.x;
    const float* xr = x + (size_t)row * DD;
    xs[d] = xr[d];
    __syncthreads();

    float acc = 0.f;
#pragma unroll
    for (int k = 0; k < KW; k++) {
        int idx = d - 3 + k;
        float xv = (idx >= 0 && idx < DD) ? xs[idx] : 0.f;
        acc += xv * cw[c * KW + k];
    }
    acc += cb[c];
    // exact GELU: 0.5*x*(1+erf(x/sqrt(2)))
    float g = 0.5f * acc * (1.f + erff(acc * 0.70710678118654752f));
    float h = (g - bm[c]) * (bg[c] * rsqrtf(bvv[c] + 1e-5f)) + bbias[c];
    g_src[(size_t)row * DD + d] = xs[d] + h;
}

// ---------------------------------------------------------------------------
// Kernel 2: QKV projection. GEMM M=57344, N=384 (q|k|v), K=128.
// 64x64 tile, 256 threads, 4x4 register micro-tile. Epilogue scatters into
// [B,H,S,hd] layout with bias.
// ---------------------------------------------------------------------------
#define BM 64
#define BN 64
#define BKT 16

__global__ void __launch_bounds__(256) k_qkv(
        const float* __restrict__ wq, const float* __restrict__ bq,
        const float* __restrict__ wk, const float* __restrict__ bk,
        const float* __restrict__ wv, const float* __restrict__ bvp) {
    __shared__ float As[BKT][68];   // [k][m], row stride 68 -> 16B aligned rows
    __shared__ float Bs[BKT][68];   // [k][n]

    int m0 = blockIdx.y * BM;
    int n0 = blockIdx.x * BN;
    int tid = threadIdx.x;
    int lr = tid >> 2;              // 0..63: row within tile (for loads)
    int lk = (tid & 3) * 4;         // k offset 0,4,8,12

    // B-matrix row pointer (concatenated wq|wk|wv, each row K-contiguous)
    int n = n0 + lr;
    const float* wrow;
    if (n < 128)      wrow = wq + (size_t)n * DD;
    else if (n < 256) wrow = wk + (size_t)(n - 128) * DD;
    else              wrow = wv + (size_t)(n - 256) * DD;

    const float* arow = g_src + (size_t)(m0 + lr) * DD;

    float acc[4][4] = {};
    int ty = tid >> 4, tx = tid & 15;

    for (int k0 = 0; k0 < DD; k0 += BKT) {
        float4 av = *(const float4*)(arow + k0 + lk);
        float4 bv = *(const float4*)(wrow + k0 + lk);
        __syncthreads();
        As[lk + 0][lr] = av.x; As[lk + 1][lr] = av.y;
        As[lk + 2][lr] = av.z; As[lk + 3][lr] = av.w;
        Bs[lk + 0][lr] = bv.x; Bs[lk + 1][lr] = bv.y;
        Bs[lk + 2][lr] = bv.z; Bs[lk + 3][lr] = bv.w;
        __syncthreads();
#pragma unroll
        for (int k = 0; k < BKT; k++) {
            float4 a4 = *(const float4*)&As[k][ty * 4];
            float4 b4 = *(const float4*)&Bs[k][tx * 4];
            float a[4] = {a4.x, a4.y, a4.z, a4.w};
            float b[4] = {b4.x, b4.y, b4.z, b4.w};
#pragma unroll
            for (int i = 0; i < 4; i++)
#pragma unroll
                for (int j = 0; j < 4; j++) acc[i][j] += a[i] * b[j];
        }
    }

    // epilogue: bias + scatter to [B,H,S,hd]
#pragma unroll
    for (int i = 0; i < 4; i++) {
        int m = m0 + ty * 4 + i;
        int b_ = m / CC, s = m % CC;
#pragma unroll
        for (int j = 0; j < 4; j++) {
            int nn = n0 + tx * 4 + j;
            int sel = nn >> 7;
            int dl = nn & 127;
            int hh = dl >> 4, hd = dl & 15;
            size_t dst = ((size_t)(b_ * HH + hh) * CC + s) * HDIM + hd;
            float v = acc[i][j];
            if (sel == 0)      g_q[dst] = v + bq[dl];
            else if (sel == 1) g_k[dst] = v + bk[dl];
            else               g_v[dst] = v + bvp[dl];
        }
    }
}

// ---------------------------------------------------------------------------
// Kernel 3: attention per (b,h). Q,K,V [112,16] + S [112,112] in smem.
// scores -> softmax -> P@V. Output written to [B,S,D] layout.
// ---------------------------------------------------------------------------
__global__ void __launch_bounds__(256) k_attn() {
    extern __shared__ float sm[];
    float* qs = sm;                     // 112*16
    float* ks = qs + CC * HDIM;
    float* vs = ks + CC * HDIM;
    float* S  = vs + CC * HDIM;         // 112*112

    int bh = blockIdx.x;
    size_t base = (size_t)bh * CC * HDIM;
    int tid = threadIdx.x;

    for (int i = tid; i < CC * HDIM; i += 256) {
        qs[i] = g_q[base + i];
        ks[i] = g_k[base + i];
        vs[i] = g_v[base + i];
    }
    __syncthreads();

    // scores: 28x28 micro-tiles of 4x4
    for (int t = tid; t < 28 * 28; t += 256) {
        int qi = (t / 28) * 4, ki = (t % 28) * 4;
        float acc[4][4] = {};
#pragma unroll
        for (int k = 0; k < HDIM; k++) {
            float a[4], b[4];
#pragma unroll
            for (int i = 0; i < 4; i++) a[i] = qs[(qi + i) * HDIM + k];
#pragma unroll
            for (int j = 0; j < 4; j++) b[j] = ks[(ki + j) * HDIM + k];
#pragma unroll
            for (int i = 0; i < 4; i++)
#pragma unroll
                for (int j = 0; j < 4; j++) acc[i][j] += a[i] * b[j];
        }
#pragma unroll
        for (int i = 0; i < 4; i++)
#pragma unroll
            for (int j = 0; j < 4; j++)
                S[(qi + i) * CC + ki + j] = acc[i][j] * 0.25f;  // SCALE = hd^-0.5
    }
    __syncthreads();

    // softmax per row (thread-per-row)
    for (int r = tid; r < CC; r += 256) {
        float* row = S + r * CC;
        float mx = row[0];
        for (int j = 1; j < CC; j++) mx = fmaxf(mx, row[j]);
        float sum = 0.f;
        for (int j = 0; j < CC; j++) { float e = expf(row[j] - mx); row[j] = e; sum += e; }
        float inv = 1.f / sum;
        for (int j = 0; j < CC; j++) row[j] *= inv;
    }
    __syncthreads();

    // out = P @ V, write to [B,S,D]
    int b_ = bh >> 3, hh = bh & 7;
    for (int t = tid; t < CC * HDIM; t += 256) {
        int qi = t / HDIM, d = t % HDIM;
        float acc = 0.f;
        for (int k = 0; k < CC; k++) acc += S[qi * CC + k] * vs[k * HDIM + d];
        g_attn[((size_t)(b_ * CC) + qi) * DD + hh * HDIM + d] = acc;
    }
}

// ---------------------------------------------------------------------------
// Kernel 4: output projection + bias + residual + LayerNorm, fused.
// Block = 32 rows x 128 cols, wo cached transposed in smem.
// ---------------------------------------------------------------------------
#define WOS 132   // k-row stride for wo_t (16B-aligned rows)
#define AOS 36    // k-row stride for ao_t

__global__ void __launch_bounds__(256) k_out(
        const float* __restrict__ wo, const float* __restrict__ bo,
        const float* __restrict__ lg, const float* __restrict__ lb,
        float* __restrict__ out) {
    extern __shared__ float sm[];
    float* wos = sm;                    // [k][n], 128*132
    float* aos = wos + 128 * WOS;       // [k][m], 128*36 (reused as y[m][n] later)

    int tid = threadIdx.x;
    int m0 = blockIdx.x * 32;

    // wo row-major [n][k] -> wos[k][n]
    for (int i = tid; i < DD * DD; i += 256) {
        int nrow = i >> 7, k = i & 127;
        wos[k * WOS + nrow] = wo[i];
    }
    // attn [m][k] -> aos[k][m]
    for (int i = tid; i < 32 * DD; i += 256) {
        int mrow = i >> 7, k = i & 127;
        aos[k * AOS + mrow] = g_attn[(size_t)(m0 + mrow) * DD + k];
    }
    __syncthreads();

    int tx = tid & 31, ty = tid >> 5;   // tx: 4-col group, ty: 4-row group
    float acc[4][4] = {};
    for (int k = 0; k < DD; k++) {
        float4 a4 = *(const float4*)&aos[k * AOS + ty * 4];
        float4 b4 = *(const float4*)&wos[k * WOS + tx * 4];
        float a[4] = {a4.x, a4.y, a4.z, a4.w};
        float b[4] = {b4.x, b4.y, b4.z, b4.w};
#pragma unroll
        for (int i = 0; i < 4; i++)
#pragma unroll
            for (int j = 0; j < 4; j++) acc[i][j] += a[i] * b[j];
    }
    __syncthreads();

    // y = proj + bias + residual(src); reuse aos region as y[m][n], stride WOS
    float* ys = aos;
#pragma unroll
    for (int i = 0; i < 4; i++) {
        int m = m0 + ty * 4 + i;
#pragma unroll
        for (int j = 0; j < 4; j++) {
            int nn = tx * 4 + j;
            ys[(ty * 4 + i) * WOS + nn] =
                acc[i][j] + bo[nn] + g_src[(size_t)m * DD + nn];
        }
    }
    __syncthreads();

    // LayerNorm: 8 warps x 4 rows, warp-shuffle reduction over 128 cols
    int lane = tid & 31, w = tid >> 5;
#pragma unroll
    for (int rr = 0; rr < 4; rr++) {
        int r = w * 4 + rr;
        float4 v4 = *(const float4*)&ys[r * WOS + lane * 4];
        float vals[4] = {v4.x, v4.y, v4.z, v4.w};
        float s1 = vals[0] + vals[1] + vals[2] + vals[3];
        float s2 = vals[0]*vals[0] + vals[1]*vals[1] + vals[2]*vals[2] + vals[3]*vals[3];
#pragma unroll
        for (int off = 16; off > 0; off >>= 1) {
            s1 += __shfl_xor_sync(0xFFFFFFFFu, s1, off);
            s2 += __shfl_xor_sync(0xFFFFFFFFu, s2, off);
        }
        float mu = s1 * (1.f / 128.f);
        float var = s2 * (1.f / 128.f) - mu * mu;
        float inv = rsqrtf(var + 1e-5f);
        int m = m0 + r;
#pragma unroll
        for (int j = 0; j < 4; j++) {
            int c = lane * 4 + j;
            out[(size_t)m * DD + c] = (vals[j] - mu) * inv * lg[c] + lb[c];
        }
    }
}

// ---------------------------------------------------------------------------
extern "C" void kernel_launch(void* const* d_in, const int* in_sizes, int n_in,
                              void* d_out, int out_size) {
    const float* x   = (const float*)d_in[0];
    const float* cw  = (const float*)d_in[1];
    const float* cb  = (const float*)d_in[2];
    const float* bg  = (const float*)d_in[3];
    const float* bb_ = (const float*)d_in[4];
    const float* bm  = (const float*)d_in[5];
    const float* bvv = (const float*)d_in[6];
    const float* wq  = (const float*)d_in[7];
    const float* bq  = (const float*)d_in[8];
    const float* wk  = (const float*)d_in[9];
    const float* bk  = (const float*)d_in[10];
    const float* wv  = (const float*)d_in[11];
    const float* bv  = (const float*)d_in[12];
    const float* wo  = (const float*)d_in[13];
    const float* bo  = (const float*)d_in[14];
    const float* lg  = (const float*)d_in[15];
    const float* lb  = (const float*)d_in[16];
    float* out = (float*)d_out;

    const int ATTN_SMEM = (3 * CC * HDIM + CC * CC) * 4;      // 71680 B
    const int OUT_SMEM  = (128 * WOS + 128 * AOS) * 4;        // 86016 B
    cudaFuncSetAttribute(k_attn, cudaFuncAttributeMaxDynamicSharedMemorySize, ATTN_SMEM);
    cudaFuncSetAttribute(k_out,  cudaFuncAttributeMaxDynamicSharedMemorySize, OUT_SMEM);

    k_conv<<<MM, 128>>>(x, cw, cb, bg, bb_, bm, bvv);
    dim3 g2(384 / BN, MM / BM);   // (6, 896)
    k_qkv<<<g2, 256>>>(wq, bq, wk, bk, wv, bv);
    k_attn<<<BB * HH, 256, ATTN_SMEM>>>();
    k_out<<<MM / 32, 256, OUT_SMEM>>>(wo, bo, lg, lb, out);
}

// round 2
// speedup vs baseline: 2.4771x; 2.4771x over previous
#include <cuda_runtime.h>
#include <cstdint>

#define BB 512
#define CC 112
#define DD 128
#define HH 8
#define HDIM 16
#define KW 8
#define MM (BB*CC)   // 57344

// Scratch (allocation-free contract)
__device__ float g_src[(size_t)MM * DD];
__device__ float g_q[(size_t)BB * HH * CC * HDIM];
__device__ float g_k[(size_t)BB * HH * CC * HDIM];
__device__ float g_v[(size_t)BB * HH * CC * HDIM];
__device__ float g_attn[(size_t)MM * DD];

// ---------------- tf32 helpers ----------------
__device__ __forceinline__ float f2tf(float v) {
    unsigned r;
    asm("cvt.rna.tf32.f32 %0, %1;" : "=r"(r) : "f"(v));
    return __uint_as_float(r);
}

__device__ __forceinline__ void mma8(float* c, const unsigned* a, const unsigned* b) {
    asm volatile(
        "mma.sync.aligned.m16n8k8.row.col.f32.tf32.tf32.f32 "
        "{%0,%1,%2,%3}, {%4,%5,%6,%7}, {%8,%9}, {%0,%1,%2,%3};"
        : "+f"(c[0]), "+f"(c[1]), "+f"(c[2]), "+f"(c[3])
        : "r"(a[0]), "r"(a[1]), "r"(a[2]), "r"(a[3]), "r"(b[0]), "r"(b[1]));
}

// ---------------------------------------------------------------------------
// Kernel 1: depthwise conv -> GELU -> BN(eval) -> residual  (unchanged)
// ---------------------------------------------------------------------------
__global__ void k_conv(const float* __restrict__ x,
                       const float* __restrict__ cw, const float* __restrict__ cb,
                       const float* __restrict__ bg, const float* __restrict__ bbias,
                       const float* __restrict__ bm, const float* __restrict__ bvv) {
    int row = blockIdx.x;
    int c = row % CC;
    __shared__ float xs[DD];
    int d = threadIdx.x;
    const float* xr = x + (size_t)row * DD;
    xs[d] = xr[d];
    __syncthreads();

    float acc = 0.f;
#pragma unroll
    for (int k = 0; k < KW; k++) {
        int idx = d - 3 + k;
        float xv = (idx >= 0 && idx < DD) ? xs[idx] : 0.f;
        acc += xv * cw[c * KW + k];
    }
    acc += cb[c];
    float g = 0.5f * acc * (1.f + erff(acc * 0.70710678118654752f));
    float h = (g - bm[c]) * (bg[c] * rsqrtf(bvv[c] + 1e-5f)) + bbias[c];
    g_src[(size_t)row * DD + d] = xs[d] + h;
}

// ---------------------------------------------------------------------------
// Kernel 2: QKV projection via tf32 MMA. M=57344, N=384, K=128.
// Block tile 128x64, 8 warps (4Mx2N), warp tile 32x32 (2x4 mma tiles).
// ---------------------------------------------------------------------------
#define AST 132

__global__ void __launch_bounds__(256) k_qkv(
        const float* __restrict__ wq, const float* __restrict__ bq,
        const float* __restrict__ wk, const float* __restrict__ bk,
        const float* __restrict__ wv, const float* __restrict__ bvp) {
    extern __shared__ float sm[];
    float* As = sm;              // [128][132]
    float* Bs = sm + 128 * AST;  // [64][132]

    int tid = threadIdx.x;
    int m0 = blockIdx.y * 128;
    int n0 = blockIdx.x * 64;
    int sel = n0 >> 7;
    int nl0 = n0 & 127;
    const float* wbase = (sel == 0) ? wq : (sel == 1) ? wk : wv;
    const float* bias  = (sel == 0) ? bq : (sel == 1) ? bk : bvp;
    float* qout = (sel == 0) ? g_q : (sel == 1) ? g_k : g_v;

    // stage A (tf32-rounded)
    const float* arow0 = g_src + (size_t)m0 * DD;
#pragma unroll
    for (int i = 0; i < 16; i++) {
        int idx = tid + i * 256;
        int row = idx >> 5, c4 = (idx & 31) * 4;
        float4 v = *(const float4*)(arow0 + row * DD + c4);
        float4 w = {f2tf(v.x), f2tf(v.y), f2tf(v.z), f2tf(v.w)};
        *(float4*)(As + row * AST + c4) = w;
    }
    // stage B
#pragma unroll
    for (int i = 0; i < 8; i++) {
        int idx = tid + i * 256;
        int row = idx >> 5, c4 = (idx & 31) * 4;
        float4 v = *(const float4*)(wbase + (size_t)(nl0 + row) * DD + c4);
        float4 w = {f2tf(v.x), f2tf(v.y), f2tf(v.z), f2tf(v.w)};
        *(float4*)(Bs + row * AST + c4) = w;
    }
    __syncthreads();

    int lane = tid & 31, warp = tid >> 5;
    int wm = warp & 3, wn = warp >> 2;
    int gr = lane >> 2, gc = lane & 3;
    const float* Abase = As + (wm * 32) * AST;
    const float* Bbase = Bs + (wn * 32) * AST;

    float c[2][4][4] = {};
#pragma unroll
    for (int k0 = 0; k0 < 128; k0 += 8) {
        unsigned a[2][4];
#pragma unroll
        for (int mi = 0; mi < 2; mi++) {
            const float* ap = Abase + (mi * 16 + gr) * AST + k0 + gc;
            a[mi][0] = __float_as_uint(ap[0]);
            a[mi][1] = __float_as_uint(ap[8 * AST]);
            a[mi][2] = __float_as_uint(ap[4]);
            a[mi][3] = __float_as_uint(ap[8 * AST + 4]);
        }
        unsigned b[4][2];
#pragma unroll
        for (int ni = 0; ni < 4; ni++) {
            const float* bp = Bbase + (ni * 8 + gr) * AST + k0 + gc;
            b[ni][0] = __float_as_uint(bp[0]);
            b[ni][1] = __float_as_uint(bp[4]);
        }
#pragma unroll
        for (int mi = 0; mi < 2; mi++)
#pragma unroll
            for (int ni = 0; ni < 4; ni++) mma8(c[mi][ni], a[mi], b[ni]);
    }

    // epilogue: bias + scatter into [B,H,S,hd]
#pragma unroll
    for (int mi = 0; mi < 2; mi++) {
#pragma unroll
        for (int ni = 0; ni < 4; ni++) {
#pragma unroll
            for (int r = 0; r < 4; r++) {
                int row = wm * 32 + mi * 16 + gr + ((r >> 1) & 1) * 8;
                int col = wn * 32 + ni * 8 + 2 * gc + (r & 1);
                int m = m0 + row;
                int dl = nl0 + col;
                int b_ = m / CC, s = m % CC;
                int h = dl >> 4, hd = dl & 15;
                size_t dst = ((size_t)(b_ * HH + h) * CC + s) * HDIM + hd;
                qout[dst] = c[mi][ni][r] + bias[dl];
            }
        }
    }
}

// ---------------------------------------------------------------------------
// Kernel 3: attention per (b,h), tf32 MMA for QK^T and PV. 224 threads.
// ---------------------------------------------------------------------------
#define QS 20
#define VST 24
#define SS 116

__global__ void __launch_bounds__(224) k_attn() {
    extern __shared__ float sm[];
    float* qs = sm;                 // [112][20]
    float* ks = qs + CC * QS;       // [112][20]
    float* vs = ks + CC * QS;       // [112][24]
    float* S  = vs + CC * VST;      // [112][116]

    int bh = blockIdx.x;
    size_t base = (size_t)bh * CC * HDIM;
    int tid = threadIdx.x;
    int lane = tid & 31, w = tid >> 5;   // w: 0..6
    int gr = lane >> 2, gc = lane & 3;

    for (int i = tid; i < CC * HDIM; i += 224) {
        int s = i >> 4, d = i & 15;
        qs[s * QS + d]  = f2tf(g_q[base + i]);
        ks[s * QS + d]  = f2tf(g_k[base + i]);
        vs[s * VST + d] = f2tf(g_v[base + i]);
    }
    __syncthreads();

    // QK^T: warp w owns m-tile rows [w*16, w*16+16)
    {
        float c[14][4] = {};
#pragma unroll
        for (int k0 = 0; k0 < 16; k0 += 8) {
            unsigned a[4];
            const float* ap = qs + (w * 16 + gr) * QS + k0 + gc;
            a[0] = __float_as_uint(ap[0]);
            a[1] = __float_as_uint(ap[8 * QS]);
            a[2] = __float_as_uint(ap[4]);
            a[3] = __float_as_uint(ap[8 * QS + 4]);
#pragma unroll
            for (int ni = 0; ni < 14; ni++) {
                unsigned b[2];
                const float* bp = ks + (ni * 8 + gr) * QS + k0 + gc;
                b[0] = __float_as_uint(bp[0]);
                b[1] = __float_as_uint(bp[4]);
                mma8(c[ni], a, b);
            }
        }
#pragma unroll
        for (int ni = 0; ni < 14; ni++) {
#pragma unroll
            for (int r = 0; r < 4; r++) {
                int row = w * 16 + gr + ((r >> 1) & 1) * 8;
                int col = ni * 8 + 2 * gc + (r & 1);
                S[row * SS + col] = c[ni][r] * 0.25f;
            }
        }
    }
    __syncthreads();

    // softmax: warp per row, 16 rows per warp
#pragma unroll
    for (int rr = 0; rr < 16; rr++) {
        int r = w * 16 + rr;
        float* row = S + r * SS;
        float v0 = row[lane];
        float v1 = row[lane + 32];
        float v2 = row[lane + 64];
        float v3 = (lane < 16) ? row[lane + 96] : -INFINITY;
        float mx = fmaxf(fmaxf(v0, v1), fmaxf(v2, v3));
#pragma unroll
        for (int off = 16; off > 0; off >>= 1)
            mx = fmaxf(mx, __shfl_xor_sync(0xFFFFFFFFu, mx, off));
        float e0 = __expf(v0 - mx), e1 = __expf(v1 - mx);
        float e2 = __expf(v2 - mx), e3 = __expf(v3 - mx);
        float sum = e0 + e1 + e2 + e3;
#pragma unroll
        for (int off = 16; off > 0; off >>= 1)
            sum += __shfl_xor_sync(0xFFFFFFFFu, sum, off);
        float inv = 1.f / sum;
        row[lane]      = f2tf(e0 * inv);
        row[lane + 32] = f2tf(e1 * inv);
        row[lane + 64] = f2tf(e2 * inv);
        if (lane < 16) row[lane + 96] = f2tf(e3 * inv);
    }
    __syncthreads();

    // PV: warp w owns m-tile w; N=16 (2 n-tiles), K=112 (14 k-steps)
    {
        float o[2][4] = {};
#pragma unroll
        for (int k0 = 0; k0 < 112; k0 += 8) {
            unsigned a[4];
            const float* ap = S + (w * 16 + gr) * SS + k0 + gc;
            a[0] = __float_as_uint(ap[0]);
            a[1] = __float_as_uint(ap[8 * SS]);
            a[2] = __float_as_uint(ap[4]);
            a[3] = __float_as_uint(ap[8 * SS + 4]);
#pragma unroll
            for (int ni = 0; ni < 2; ni++) {
                unsigned b[2];
                const float* bp = vs + (k0 + gc) * VST + ni * 8 + gr;
                b[0] = __float_as_uint(bp[0]);
                b[1] = __float_as_uint(bp[4 * VST]);
                mma8(o[ni], a, b);
            }
        }
        int b_ = bh >> 3, h = bh & 7;
#pragma unroll
        for (int ni = 0; ni < 2; ni++) {
#pragma unroll
            for (int r = 0; r < 4; r++) {
                int s = w * 16 + gr + ((r >> 1) & 1) * 8;
                int hd = ni * 8 + 2 * gc + (r & 1);
                g_attn[((size_t)(b_ * CC) + s) * DD + h * HDIM + hd] = o[ni][r];
            }
        }
    }
}

// ---------------------------------------------------------------------------
// Kernel 4: output projection (tf32 MMA) + bias + residual + LayerNorm.
// Block tile 64x128, 8 warps (2Mx4N), warp tile 32x32.
// ---------------------------------------------------------------------------
__global__ void __launch_bounds__(256) k_out(
        const float* __restrict__ wo, const float* __restrict__ bo,
        const float* __restrict__ lg, const float* __restrict__ lb,
        float* __restrict__ out) {
    extern __shared__ float sm[];
    float* Ws = sm;                 // [128][132]
    float* Xs = sm + 128 * AST;     // [64][132]; reused as y after GEMM

    int tid = threadIdx.x;
    int m0 = blockIdx.x * 64;

#pragma unroll
    for (int i = 0; i < 16; i++) {
        int idx = tid + i * 256;
        int row = idx >> 5, c4 = (idx & 31) * 4;
        float4 v = *(const float4*)(wo + row * DD + c4);
        float4 wv4 = {f2tf(v.x), f2tf(v.y), f2tf(v.z), f2tf(v.w)};
        *(float4*)(Ws + row * AST + c4) = wv4;
    }
#pragma unroll
    for (int i = 0; i < 8; i++) {
        int idx = tid + i * 256;
        int row = idx >> 5, c4 = (idx & 31) * 4;
        float4 v = *(const float4*)(g_attn + (size_t)(m0 + row) * DD + c4);
        float4 wv4 = {f2tf(v.x), f2tf(v.y), f2tf(v.z), f2tf(v.w)};
        *(float4*)(Xs + row * AST + c4) = wv4;
    }
    __syncthreads();

    int lane = tid & 31, warp = tid >> 5;
    int wm = warp & 1, wn = warp >> 1;   // 2 x 4
    int gr = lane >> 2, gc = lane & 3;
    const float* Abase = Xs + (wm * 32) * AST;
    const float* Bbase = Ws + (wn * 32) * AST;

    float c[2][4][4] = {};
#pragma unroll
    for (int k0 = 0; k0 < 128; k0 += 8) {
        unsigned a[2][4];
#pragma unroll
        for (int mi = 0; mi < 2; mi++) {
            const float* ap = Abase + (mi * 16 + gr) * AST + k0 + gc;
            a[mi][0] = __float_as_uint(ap[0]);
            a[mi][1] = __float_as_uint(ap[8 * AST]);
            a[mi][2] = __float_as_uint(ap[4]);
            a[mi][3] = __float_as_uint(ap[8 * AST + 4]);
        }
        unsigned b[4][2];
#pragma unroll
        for (int ni = 0; ni < 4; ni++) {
            const float* bp = Bbase + (ni * 8 + gr) * AST + k0 + gc;
            b[ni][0] = __float_as_uint(bp[0]);
            b[ni][1] = __float_as_uint(bp[4]);
        }
#pragma unroll
        for (int mi = 0; mi < 2; mi++)
#pragma unroll
            for (int ni = 0; ni < 4; ni++) mma8(c[mi][ni], a[mi], b[ni]);
    }
    __syncthreads();   // done reading Xs; safe to overwrite as y

    float* ys = Xs;
#pragma unroll
    for (int mi = 0; mi < 2; mi++) {
#pragma unroll
        for (int ni = 0; ni < 4; ni++) {
#pragma unroll
            for (int r = 0; r < 4; r++) {
                int row = wm * 32 + mi * 16 + gr + ((r >> 1) & 1) * 8;
                int col = wn * 32 + ni * 8 + 2 * gc + (r & 1);
                int m = m0 + row;
                ys[row * AST + col] =
                    c[mi][ni][r] + bo[col] + g_src[(size_t)m * DD + col];
            }
        }
    }
    __syncthreads();

    // LayerNorm: warp per row, 8 rows per warp
#pragma unroll
    for (int rr = 0; rr < 8; rr++) {
        int r = warp * 8 + rr;
        float4 v4 = *(const float4*)(ys + r * AST + lane * 4);
        float vals[4] = {v4.x, v4.y, v4.z, v4.w};
        float s1 = vals[0] + vals[1] + vals[2] + vals[3];
        float s2 = vals[0]*vals[0] + vals[1]*vals[1] + vals[2]*vals[2] + vals[3]*vals[3];
#pragma unroll
        for (int off = 16; off > 0; off >>= 1) {
            s1 += __shfl_xor_sync(0xFFFFFFFFu, s1, off);
            s2 += __shfl_xor_sync(0xFFFFFFFFu, s2, off);
        }
        float mu = s1 * (1.f / 128.f);
        float var = s2 * (1.f / 128.f) - mu * mu;
        float inv = rsqrtf(var + 1e-5f);
        int m = m0 + r;
#pragma unroll
        for (int j = 0; j < 4; j++) {
            int cidx = lane * 4 + j;
            out[(size_t)m * DD + cidx] = (vals[j] - mu) * inv * lg[cidx] + lb[cidx];
        }
    }
}

// ---------------------------------------------------------------------------
extern "C" void kernel_launch(void* const* d_in, const int* in_sizes, int n_in,
                              void* d_out, int out_size) {
    const float* x   = (const float*)d_in[0];
    const float* cw  = (const float*)d_in[1];
    const float* cb  = (const float*)d_in[2];
    const float* bg  = (const float*)d_in[3];
    const float* bb_ = (const float*)d_in[4];
    const float* bm  = (const float*)d_in[5];
    const float* bvv = (const float*)d_in[6];
    const float* wq  = (const float*)d_in[7];
    const float* bq  = (const float*)d_in[8];
    const float* wk  = (const float*)d_in[9];
    const float* bk  = (const float*)d_in[10];
    const float* wv  = (const float*)d_in[11];
    const float* bv  = (const float*)d_in[12];
    const float* wo  = (const float*)d_in[13];
    const float* bo  = (const float*)d_in[14];
    const float* lg  = (const float*)d_in[15];
    const float* lb  = (const float*)d_in[16];
    float* out = (float*)d_out;

    const int QKV_SMEM  = (128 * AST + 64 * AST) * 4;                     // 101376
    const int ATTN_SMEM = (2 * CC * QS + CC * VST + CC * SS) * 4;         // 80640
    const int OUT_SMEM  = (128 * AST + 64 * AST) * 4;                     // 101376
    cudaFuncSetAttribute(k_qkv,  cudaFuncAttributeMaxDynamicSharedMemorySize, QKV_SMEM);
    cudaFuncSetAttribute(k_attn, cudaFuncAttributeMaxDynamicSharedMemorySize, ATTN_SMEM);
    cudaFuncSetAttribute(k_out,  cudaFuncAttributeMaxDynamicSharedMemorySize, OUT_SMEM);

    k_conv<<<MM, 128>>>(x, cw, cb, bg, bb_, bm, bvv);
    dim3 g2(6, MM / 128);    // N tiles x M tiles
    k_qkv<<<g2, 256, QKV_SMEM>>>(wq, bq, wk, bk, wv, bv);
    k_attn<<<BB * HH, 224, ATTN_SMEM>>>();
    k_out<<<MM / 64, 256, OUT_SMEM>>>(wo, bo, lg, lb, out);
}

// round 3
// speedup vs baseline: 3.4279x; 1.3838x over previous
#include <cuda_runtime.h>
#include <cuda_bf16.h>
#include <cstdint>

#define BB 512
#define CC 112
#define DD 128
#define HH 8
#define HDIM 16
#define KW 8
#define MM (BB*CC)   // 57344

// Scratch (allocation-free contract)
__device__ float g_src[(size_t)MM * DD];                      // fp32 residual
__device__ __nv_bfloat16 g_q[(size_t)BB * HH * CC * HDIM];    // [B,H,S,hd]
__device__ __nv_bfloat16 g_k[(size_t)BB * HH * CC * HDIM];    // [B,H,S,hd]
__device__ __nv_bfloat16 g_v[(size_t)BB * HH * HDIM * CC];    // [B,H,hd,S] (transposed!)
__device__ __nv_bfloat16 g_attn[(size_t)MM * DD];             // [B,S,D]

__device__ __forceinline__ unsigned packbf(float a, float b) {
    __nv_bfloat162 p = __floats2bfloat162_rn(a, b);
    return *reinterpret_cast<unsigned*>(&p);
}

__device__ __forceinline__ void mma16(float* c, const unsigned* a, const unsigned* b) {
    asm volatile(
        "mma.sync.aligned.m16n8k16.row.col.f32.bf16.bf16.f32 "
        "{%0,%1,%2,%3}, {%4,%5,%6,%7}, {%8,%9}, {%0,%1,%2,%3};"
        : "+f"(c[0]), "+f"(c[1]), "+f"(c[2]), "+f"(c[3])
        : "r"(a[0]), "r"(a[1]), "r"(a[2]), "r"(a[3]), "r"(b[0]), "r"(b[1]));
}

// ---------------------------------------------------------------------------
// Kernel 1: depthwise conv -> GELU -> BN(eval) -> residual (fp32, exact)
// ---------------------------------------------------------------------------
__global__ void k_conv(const float* __restrict__ x,
                       const float* __restrict__ cw, const float* __restrict__ cb,
                       const float* __restrict__ bg, const float* __restrict__ bbias,
                       const float* __restrict__ bm, const float* __restrict__ bvv) {
    int row = blockIdx.x;
    int c = row % CC;
    __shared__ float xs[DD];
    int d = threadIdx.x;
    const float* xr = x + (size_t)row * DD;
    xs[d] = xr[d];
    __syncthreads();

    float acc = 0.f;
#pragma unroll
    for (int k = 0; k < KW; k++) {
        int idx = d - 3 + k;
        float xv = (idx >= 0 && idx < DD) ? xs[idx] : 0.f;
        acc += xv * cw[c * KW + k];
    }
    acc += cb[c];
    float g = 0.5f * acc * (1.f + erff(acc * 0.70710678118654752f));
    float h = (g - bm[c]) * (bg[c] * rsqrtf(bvv[c] + 1e-5f)) + bbias[c];
    g_src[(size_t)row * DD + d] = xs[d] + h;
}

// ---------------------------------------------------------------------------
// Kernel 2: QKV projection, bf16 MMA. Block 128x64, 8 warps (4Mx2N).
// smem stride: 68 u32 words (136 bf16) -> conflict-free fragment loads.
// ---------------------------------------------------------------------------
__global__ void __launch_bounds__(256) k_qkv(
        const float* __restrict__ wq, const float* __restrict__ bq,
        const float* __restrict__ wk, const float* __restrict__ bk,
        const float* __restrict__ wv, const float* __restrict__ bvp) {
    extern __shared__ unsigned smu[];
    unsigned* Asu = smu;            // [128][68] u32 (bf16 pairs along k)
    unsigned* Bsu = smu + 128 * 68; // [64][68]

    int tid = threadIdx.x;
    int m0 = blockIdx.y * 128;
    int n0 = blockIdx.x * 64;
    int sel = n0 >> 7;
    int nl0 = n0 & 127;
    const float* wbase = (sel == 0) ? wq : (sel == 1) ? wk : wv;
    const float* bias  = (sel == 0) ? bq : (sel == 1) ? bk : bvp;

    // stage A: g_src fp32 -> bf16 pairs
    const float* arow0 = g_src + (size_t)m0 * DD;
#pragma unroll
    for (int i = 0; i < 16; i++) {
        int idx = tid + i * 256;
        int row = idx >> 5, c4 = (idx & 31) * 4;
        float4 v = *(const float4*)(arow0 + row * DD + c4);
        Asu[row * 68 + (c4 >> 1)]     = packbf(v.x, v.y);
        Asu[row * 68 + (c4 >> 1) + 1] = packbf(v.z, v.w);
    }
    // stage B: weights fp32 -> bf16 pairs
#pragma unroll
    for (int i = 0; i < 8; i++) {
        int idx = tid + i * 256;
        int row = idx >> 5, c4 = (idx & 31) * 4;
        float4 v = *(const float4*)(wbase + (size_t)(nl0 + row) * DD + c4);
        Bsu[row * 68 + (c4 >> 1)]     = packbf(v.x, v.y);
        Bsu[row * 68 + (c4 >> 1) + 1] = packbf(v.z, v.w);
    }
    __syncthreads();

    int lane = tid & 31, warp = tid >> 5;
    int wm = warp & 3, wn = warp >> 2;
    int gr = lane >> 2, gc = lane & 3;

    float c[2][4][4] = {};
#pragma unroll
    for (int kw = 0; kw < 64; kw += 8) {   // k0 = 2*kw
        unsigned a[2][4];
#pragma unroll
        for (int mi = 0; mi < 2; mi++) {
            const unsigned* ap = Asu + (wm * 32 + mi * 16 + gr) * 68 + kw + gc;
            a[mi][0] = ap[0];
            a[mi][1] = ap[8 * 68];
            a[mi][2] = ap[4];
            a[mi][3] = ap[8 * 68 + 4];
        }
        unsigned b[4][2];
#pragma unroll
        for (int ni = 0; ni < 4; ni++) {
            const unsigned* bp = Bsu + (wn * 32 + ni * 8 + gr) * 68 + kw + gc;
            b[ni][0] = bp[0];
            b[ni][1] = bp[4];
        }
#pragma unroll
        for (int mi = 0; mi < 2; mi++)
#pragma unroll
            for (int ni = 0; ni < 4; ni++) mma16(c[mi][ni], a[mi], b[ni]);
    }

    // epilogue: bias + bf16 store. q/k: [B,H,S,hd] paired; v: [B,H,hd,S] transposed
#pragma unroll
    for (int mi = 0; mi < 2; mi++) {
#pragma unroll
        for (int ni = 0; ni < 4; ni++) {
#pragma unroll
            for (int r2 = 0; r2 < 2; r2++) {
                int row = wm * 32 + mi * 16 + gr + r2 * 8;
                int col = wn * 32 + ni * 8 + 2 * gc;
                int m = m0 + row;
                int dl = nl0 + col;
                int b_ = m / CC, s = m % CC;
                int h = dl >> 4, hd = dl & 15;
                float v0 = c[mi][ni][2 * r2]     + bias[dl];
                float v1 = c[mi][ni][2 * r2 + 1] + bias[dl + 1];
                if (sel == 0) {
                    size_t dst = ((size_t)(b_ * HH + h) * CC + s) * HDIM + hd;
                    __nv_bfloat162 p = __floats2bfloat162_rn(v0, v1);
                    *(__nv_bfloat162*)&g_q[dst] = p;
                } else if (sel == 1) {
                    size_t dst = ((size_t)(b_ * HH + h) * CC + s) * HDIM + hd;
                    __nv_bfloat162 p = __floats2bfloat162_rn(v0, v1);
                    *(__nv_bfloat162*)&g_k[dst] = p;
                } else {
                    size_t dstT = ((size_t)(b_ * HH + h) * HDIM + hd) * CC + s;
                    g_v[dstT]      = __float2bfloat16(v0);
                    g_v[dstT + CC] = __float2bfloat16(v1);
                }
            }
        }
    }
}

// ---------------------------------------------------------------------------
// Kernel 3: attention per (b,h), bf16 MMA. 7 warps; warp w owns rows
// [16w,16w+16) through QK^T, softmax and PV (warp-local, __syncwarp only).
// ---------------------------------------------------------------------------
__global__ void __launch_bounds__(224) k_attn() {
    extern __shared__ unsigned smu[];
    unsigned* qsu = smu;            // [112][12] u32 (24 bf16/row: 16 used)
    unsigned* ksu = smu + 1344;     // [112][12]
    unsigned* vtu = smu + 2688;     // [16][60]  (row hd, 112 bf16 over s)
    float*    S   = (float*)(smu + 3648);  // [112][116] fp32 scores
    unsigned* SPu = smu + 16640;    // [112][60] bf16 probs (120/row, 112 used)

    int bh = blockIdx.x;
    size_t base = (size_t)bh * CC * HDIM;
    int tid = threadIdx.x;
    int lane = tid & 31, w = tid >> 5;
    int gr = lane >> 2, gc = lane & 3;

    // staging: raw u32 pair copies (sources already bf16 in the right layouts)
    const unsigned* qsrc = (const unsigned*)(g_q + base);
    const unsigned* ksrc = (const unsigned*)(g_k + base);
    const unsigned* vsrc = (const unsigned*)(g_v + base);
    for (int i = tid; i < 896; i += 224) {
        int s = i >> 3, dp = i & 7;
        qsu[s * 12 + dp] = qsrc[i];
        ksu[s * 12 + dp] = ksrc[i];
    }
    for (int i = tid; i < 896; i += 224) {   // 16 hd-rows x 56 words
        int hd = i / 56, sp = i % 56;
        vtu[hd * 60 + sp] = vsrc[i];
    }
    __syncthreads();

    // QK^T: single k16 step, 14 n-tiles
    {
        unsigned a[4];
        const unsigned* ap = qsu + (w * 16 + gr) * 12 + gc;
        a[0] = ap[0];
        a[1] = ap[8 * 12];
        a[2] = ap[4];
        a[3] = ap[8 * 12 + 4];
#pragma unroll
        for (int ni = 0; ni < 14; ni++) {
            float c[4] = {};
            unsigned b[2];
            const unsigned* bp = ksu + (ni * 8 + gr) * 12 + gc;
            b[0] = bp[0];
            b[1] = bp[4];
            mma16(c, a, b);
            int col = ni * 8 + 2 * gc;
            *(float2*)&S[(w * 16 + gr) * 116 + col]     = make_float2(c[0] * 0.25f, c[1] * 0.25f);
            *(float2*)&S[(w * 16 + gr + 8) * 116 + col] = make_float2(c[2] * 0.25f, c[3] * 0.25f);
        }
    }
    __syncwarp();

    // softmax: warp per row, 16 rows; write bf16 probs to SP
    __nv_bfloat16* SPh = (__nv_bfloat16*)SPu;
#pragma unroll
    for (int rr = 0; rr < 16; rr++) {
        int r = w * 16 + rr;
        const float* row = S + r * 116;
        float v0 = row[lane];
        float v1 = row[lane + 32];
        float v2 = row[lane + 64];
        float v3 = (lane < 16) ? row[lane + 96] : -INFINITY;
        float mx = fmaxf(fmaxf(v0, v1), fmaxf(v2, v3));
#pragma unroll
        for (int off = 16; off > 0; off >>= 1)
            mx = fmaxf(mx, __shfl_xor_sync(0xFFFFFFFFu, mx, off));
        float e0 = __expf(v0 - mx), e1 = __expf(v1 - mx);
        float e2 = __expf(v2 - mx), e3 = __expf(v3 - mx);
        float sum = e0 + e1 + e2 + e3;
#pragma unroll
        for (int off = 16; off > 0; off >>= 1)
            sum += __shfl_xor_sync(0xFFFFFFFFu, sum, off);
        float inv = 1.f / sum;
        __nv_bfloat16* sp = SPh + r * 120;
        sp[lane]      = __float2bfloat16(e0 * inv);
        sp[lane + 32] = __float2bfloat16(e1 * inv);
        sp[lane + 64] = __float2bfloat16(e2 * inv);
        if (lane < 16) sp[lane + 96] = __float2bfloat16(e3 * inv);
    }
    __syncwarp();

    // PV: K=112 (7 k16 steps), N=16 (2 n-tiles)
    {
        float o[2][4] = {};
#pragma unroll
        for (int kw = 0; kw < 56; kw += 8) {
            unsigned a[4];
            const unsigned* ap = SPu + (w * 16 + gr) * 60 + kw + gc;
            a[0] = ap[0];
            a[1] = ap[8 * 60];
            a[2] = ap[4];
            a[3] = ap[8 * 60 + 4];
#pragma unroll
            for (int ni = 0; ni < 2; ni++) {
                unsigned b[2];
                const unsigned* bp = vtu + (ni * 8 + gr) * 60 + kw + gc;
                b[0] = bp[0];
                b[1] = bp[4];
                mma16(o[ni], a, b);
            }
        }
        int b_ = bh >> 3, h = bh & 7;
#pragma unroll
        for (int ni = 0; ni < 2; ni++) {
#pragma unroll
            for (int r2 = 0; r2 < 2; r2++) {
                int s = w * 16 + gr + r2 * 8;
                int hd = ni * 8 + 2 * gc;
                size_t dst = ((size_t)(b_ * CC) + s) * DD + h * HDIM + hd;
                __nv_bfloat162 p = __floats2bfloat162_rn(o[ni][2 * r2], o[ni][2 * r2 + 1]);
                *(__nv_bfloat162*)&g_attn[dst] = p;
            }
        }
    }
}

// ---------------------------------------------------------------------------
// Kernel 4: output projection (bf16 MMA) + bias + residual(fp32) + LayerNorm.
// Block 64x128, 8 warps (2Mx4N). ys overlays Ws after GEMM.
// ---------------------------------------------------------------------------
__global__ void __launch_bounds__(256) k_out(
        const float* __restrict__ wo, const float* __restrict__ bo,
        const float* __restrict__ lg, const float* __restrict__ lb,
        float* __restrict__ out) {
    extern __shared__ unsigned smu[];
    unsigned* Wsu = smu;            // [128][68]
    unsigned* Xsu = smu + 128 * 68; // [64][68]

    int tid = threadIdx.x;
    int m0 = blockIdx.x * 64;

#pragma unroll
    for (int i = 0; i < 16; i++) {
        int idx = tid + i * 256;
        int row = idx >> 5, c4 = (idx & 31) * 4;
        float4 v = *(const float4*)(wo + row * DD + c4);
        Wsu[row * 68 + (c4 >> 1)]     = packbf(v.x, v.y);
        Wsu[row * 68 + (c4 >> 1) + 1] = packbf(v.z, v.w);
    }
    // X: g_attn already bf16 -> uint4 copies
    const uint4* asrc = (const uint4*)g_attn;
#pragma unroll
    for (int i = 0; i < 4; i++) {
        int idx = tid + i * 256;
        int row = idx >> 4, q4 = (idx & 15) * 4;
        *(uint4*)(Xsu + row * 68 + q4) = asrc[(size_t)(m0 + row) * 16 + (q4 >> 2)];
    }
    __syncthreads();

    int lane = tid & 31, warp = tid >> 5;
    int wm = warp & 1, wn = warp >> 1;
    int gr = lane >> 2, gc = lane & 3;

    float c[2][4][4] = {};
#pragma unroll
    for (int kw = 0; kw < 64; kw += 8) {
        unsigned a[2][4];
#pragma unroll
        for (int mi = 0; mi < 2; mi++) {
            const unsigned* ap = Xsu + (wm * 32 + mi * 16 + gr) * 68 + kw + gc;
            a[mi][0] = ap[0];
            a[mi][1] = ap[8 * 68];
            a[mi][2] = ap[4];
            a[mi][3] = ap[8 * 68 + 4];
        }
        unsigned b[4][2];
#pragma unroll
        for (int ni = 0; ni < 4; ni++) {
            const unsigned* bp = Wsu + (wn * 32 + ni * 8 + gr) * 68 + kw + gc;
            b[ni][0] = bp[0];
            b[ni][1] = bp[4];
        }
#pragma unroll
        for (int mi = 0; mi < 2; mi++)
#pragma unroll
            for (int ni = 0; ni < 4; ni++) mma16(c[mi][ni], a[mi], b[ni]);
    }
    __syncthreads();   // done with Ws/Xs; overlay ys

    float* ys = (float*)smu;        // [64][132]
#pragma unroll
    for (int mi = 0; mi < 2; mi++) {
#pragma unroll
        for (int ni = 0; ni < 4; ni++) {
#pragma unroll
            for (int r = 0; r < 4; r++) {
                int row = wm * 32 + mi * 16 + gr + ((r >> 1) & 1) * 8;
                int col = wn * 32 + ni * 8 + 2 * gc + (r & 1);
                int m = m0 + row;
                ys[row * 132 + col] =
                    c[mi][ni][r] + bo[col] + g_src[(size_t)m * DD + col];
            }
        }
    }
    __syncthreads();

    // LayerNorm: warp per row, 8 rows per warp
#pragma unroll
    for (int rr = 0; rr < 8; rr++) {
        int r = warp * 8 + rr;
        float4 v4 = *(const float4*)(ys + r * 132 + lane * 4);
        float vals[4] = {v4.x, v4.y, v4.z, v4.w};
        float s1 = vals[0] + vals[1] + vals[2] + vals[3];
        float s2 = vals[0]*vals[0] + vals[1]*vals[1] + vals[2]*vals[2] + vals[3]*vals[3];
#pragma unroll
        for (int off = 16; off > 0; off >>= 1) {
            s1 += __shfl_xor_sync(0xFFFFFFFFu, s1, off);
            s2 += __shfl_xor_sync(0xFFFFFFFFu, s2, off);
        }
        float mu = s1 * (1.f / 128.f);
        float var = s2 * (1.f / 128.f) - mu * mu;
        float inv = rsqrtf(var + 1e-5f);
        int m = m0 + r;
#pragma unroll
        for (int j = 0; j < 4; j++) {
            int cidx = lane * 4 + j;
            out[(size_t)m * DD + cidx] = (vals[j] - mu) * inv * lg[cidx] + lb[cidx];
        }
    }
}

// ---------------------------------------------------------------------------
extern "C" void kernel_launch(void* const* d_in, const int* in_sizes, int n_in,
                              void* d_out, int out_size) {
    const float* x   = (const float*)d_in[0];
    const float* cw  = (const float*)d_in[1];
    const float* cb  = (const float*)d_in[2];
    const float* bg  = (const float*)d_in[3];
    const float* bb_ = (const float*)d_in[4];
    const float* bm  = (const float*)d_in[5];
    const float* bvv = (const float*)d_in[6];
    const float* wq  = (const float*)d_in[7];
    const float* bq  = (const float*)d_in[8];
    const float* wk  = (const float*)d_in[9];
    const float* bk  = (const float*)d_in[10];
    const float* wv  = (const float*)d_in[11];
    const float* bv  = (const float*)d_in[12];
    const float* wo  = (const float*)d_in[13];
    const float* bo  = (const float*)d_in[14];
    const float* lg  = (const float*)d_in[15];
    const float* lb  = (const float*)d_in[16];
    float* out = (float*)d_out;

    const int QKV_SMEM  = (128 + 64) * 68 * 4;      // 52224
    const int ATTN_SMEM = 23360 * 4;                // 93440
    const int OUT_SMEM  = (128 + 64) * 68 * 4;      // 52224
    cudaFuncSetAttribute(k_qkv,  cudaFuncAttributeMaxDynamicSharedMemorySize, QKV_SMEM);
    cudaFuncSetAttribute(k_attn, cudaFuncAttributeMaxDynamicSharedMemorySize, ATTN_SMEM);
    cudaFuncSetAttribute(k_out,  cudaFuncAttributeMaxDynamicSharedMemorySize, OUT_SMEM);

    k_conv<<<MM, 128>>>(x, cw, cb, bg, bb_, bm, bvv);
    dim3 g2(6, MM / 128);     // 6 x 448
    k_qkv<<<g2, 256, QKV_SMEM>>>(wq, bq, wk, bk, wv, bv);
    k_attn<<<BB * HH, 224, ATTN_SMEM>>>();
    k_out<<<MM / 64, 256, OUT_SMEM>>>(wo, bo, lg, lb, out);
}

// round 4
// speedup vs baseline: 3.8643x; 1.1273x over previous
#include <cuda_runtime.h>
#include <cuda_bf16.h>
#include <cstdint>

#define BB 512
#define CC 112
#define DD 128
#define HH 8
#define HDIM 16
#define KW 8
#define MM (BB*CC)   // 57344

// Scratch (allocation-free contract)
__device__ float g_src[(size_t)MM * DD];                      // fp32 residual
__device__ __nv_bfloat16 g_srcb[(size_t)MM * DD];             // bf16 copy for GEMM A
__device__ __nv_bfloat16 g_q[(size_t)BB * HH * CC * HDIM];    // [B,H,S,hd]
__device__ __nv_bfloat16 g_k[(size_t)BB * HH * CC * HDIM];    // [B,H,S,hd]
__device__ __nv_bfloat16 g_v[(size_t)BB * HH * HDIM * CC];    // [B,H,hd,S] transposed
__device__ __nv_bfloat16 g_attn[(size_t)MM * DD];             // [B,S,D]

__device__ __forceinline__ unsigned packbf(float a, float b) {
    __nv_bfloat162 p = __floats2bfloat162_rn(a, b);
    return *reinterpret_cast<unsigned*>(&p);
}

__device__ __forceinline__ void mma16(float* c, const unsigned* a, const unsigned* b) {
    asm volatile(
        "mma.sync.aligned.m16n8k16.row.col.f32.bf16.bf16.f32 "
        "{%0,%1,%2,%3}, {%4,%5,%6,%7}, {%8,%9}, {%0,%1,%2,%3};"
        : "+f"(c[0]), "+f"(c[1]), "+f"(c[2]), "+f"(c[3])
        : "r"(a[0]), "r"(a[1]), "r"(a[2]), "r"(a[3]), "r"(b[0]), "r"(b[1]));
}

__device__ __forceinline__ void ldsm4(unsigned* r, unsigned addr) {
    asm volatile("ldmatrix.sync.aligned.m8n8.x4.shared.b16 {%0,%1,%2,%3}, [%4];"
        : "=r"(r[0]), "=r"(r[1]), "=r"(r[2]), "=r"(r[3]) : "r"(addr));
}

__device__ __forceinline__ unsigned su(const void* p) {
    return (unsigned)__cvta_generic_to_shared(p);
}

// ---------------------------------------------------------------------------
// Kernel 1: depthwise conv -> GELU -> BN -> residual; writes fp32 + bf16 src
// ---------------------------------------------------------------------------
__global__ void k_conv(const float* __restrict__ x,
                       const float* __restrict__ cw, const float* __restrict__ cb,
                       const float* __restrict__ bg, const float* __restrict__ bbias,
                       const float* __restrict__ bm, const float* __restrict__ bvv) {
    int row = blockIdx.x;
    int c = row % CC;
    __shared__ float xs[DD];
    int d = threadIdx.x;
    const float* xr = x + (size_t)row * DD;
    xs[d] = xr[d];
    __syncthreads();

    float acc = 0.f;
#pragma unroll
    for (int k = 0; k < KW; k++) {
        int idx = d - 3 + k;
        float xv = (idx >= 0 && idx < DD) ? xs[idx] : 0.f;
        acc += xv * cw[c * KW + k];
    }
    acc += cb[c];
    float g = 0.5f * acc * (1.f + erff(acc * 0.70710678118654752f));
    float h = (g - bm[c]) * (bg[c] * rsqrtf(bvv[c] + 1e-5f)) + bbias[c];
    float s = xs[d] + h;
    g_src[(size_t)row * DD + d]  = s;
    g_srcb[(size_t)row * DD + d] = __float2bfloat16(s);
}

// ---------------------------------------------------------------------------
// Kernel 2: QKV projection. Block = 128 rows x 384 cols (3-iter n-loop).
// 8 warps, warp tile 64x32 (2M x 4N groups). ldmatrix fragment loads.
// ---------------------------------------------------------------------------
__global__ void __launch_bounds__(256) k_qkv(
        const float* __restrict__ wq, const float* __restrict__ bq,
        const float* __restrict__ wk, const float* __restrict__ bk,
        const float* __restrict__ wv, const float* __restrict__ bvp) {
    extern __shared__ unsigned smu[];
    unsigned* Asu = smu;             // [128][68]
    unsigned* Bsu = smu + 128 * 68;  // [128][68]

    int tid = threadIdx.x;
    int m0 = blockIdx.x * 128;
    int lane = tid & 31, warp = tid >> 5;
    int wm = warp >> 2, wn = warp & 3;
    int gr = lane >> 2, gc = lane & 3;

    // stage A once: bf16 src, raw uint4 copies
    const uint4* asrc = (const uint4*)g_srcb;
#pragma unroll
    for (int i = 0; i < 8; i++) {
        int idx = tid + i * 256;
        int row = idx >> 4, q4 = idx & 15;
        *(uint4*)(Asu + row * 68 + q4 * 4) = asrc[(size_t)(m0 + row) * 16 + q4];
    }

    // ldmatrix lane addressing
    int arow = (lane & 7) + ((lane >> 3) & 1) * 8;
    int acolw = (lane >> 4) * 4;
    int brow = (lane & 7) + ((lane >> 4) & 1) * 8;
    int bcolw = ((lane >> 3) & 1) * 4;

    unsigned abase[4], bbase[2];
#pragma unroll
    for (int mi = 0; mi < 4; mi++)
        abase[mi] = su(Asu + (wm * 64 + mi * 16 + arow) * 68 + acolw);
#pragma unroll
    for (int bj = 0; bj < 2; bj++)
        bbase[bj] = su(Bsu + (wn * 32 + bj * 16 + brow) * 68 + bcolw);

    for (int sel = 0; sel < 3; sel++) {
        const float* wbase = (sel == 0) ? wq : (sel == 1) ? wk : wv;
        const float* bias  = (sel == 0) ? bq : (sel == 1) ? bk : bvp;

        __syncthreads();   // previous iter's mma done before restaging B
        // stage B: 128x128 weights fp32 -> bf16
#pragma unroll
        for (int i = 0; i < 16; i++) {
            int idx = tid + i * 256;
            int row = idx >> 5, c4 = (idx & 31) * 4;
            float4 v = *(const float4*)(wbase + (size_t)row * DD + c4);
            Bsu[row * 68 + (c4 >> 1)]     = packbf(v.x, v.y);
            Bsu[row * 68 + (c4 >> 1) + 1] = packbf(v.z, v.w);
        }
        __syncthreads();

        float c[4][4][4] = {};
#pragma unroll
        for (int kw = 0; kw < 64; kw += 8) {
            unsigned a[4][4], b[2][4];
#pragma unroll
            for (int mi = 0; mi < 4; mi++) ldsm4(a[mi], abase[mi] + kw * 4);
#pragma unroll
            for (int bj = 0; bj < 2; bj++) ldsm4(b[bj], bbase[bj] + kw * 4);
#pragma unroll
            for (int mi = 0; mi < 4; mi++)
#pragma unroll
                for (int ni = 0; ni < 4; ni++)
                    mma16(c[mi][ni], a[mi], &b[ni >> 1][(ni & 1) * 2]);
        }

        // epilogue
#pragma unroll
        for (int mi = 0; mi < 4; mi++) {
#pragma unroll
            for (int ni = 0; ni < 4; ni++) {
#pragma unroll
                for (int r2 = 0; r2 < 2; r2++) {
                    int row = wm * 64 + mi * 16 + gr + r2 * 8;
                    int col = wn * 32 + ni * 8 + 2 * gc;
                    int m = m0 + row;
                    int b_ = m / CC, s = m % CC;
                    int h = col >> 4, hd = col & 15;
                    float v0 = c[mi][ni][2 * r2]     + bias[col];
                    float v1 = c[mi][ni][2 * r2 + 1] + bias[col + 1];
                    if (sel == 0) {
                        size_t dst = ((size_t)(b_ * HH + h) * CC + s) * HDIM + hd;
                        *(__nv_bfloat162*)&g_q[dst] = __floats2bfloat162_rn(v0, v1);
                    } else if (sel == 1) {
                        size_t dst = ((size_t)(b_ * HH + h) * CC + s) * HDIM + hd;
                        *(__nv_bfloat162*)&g_k[dst] = __floats2bfloat162_rn(v0, v1);
                    } else {
                        size_t dstT = ((size_t)(b_ * HH + h) * HDIM + hd) * CC + s;
                        g_v[dstT]      = __float2bfloat16(v0);
                        g_v[dstT + CC] = __float2bfloat16(v1);
                    }
                }
            }
        }
    }
}

// ---------------------------------------------------------------------------
// Kernel 3: attention per (b,h), bf16 MMA + ldmatrix. 7 warps; warp w owns
// rows [16w,16w+16) through all three stages.
// ---------------------------------------------------------------------------
__global__ void __launch_bounds__(224) k_attn() {
    extern __shared__ unsigned smu[];
    unsigned* qsu = smu;            // [112][12]
    unsigned* ksu = smu + 1344;     // [112][12]
    unsigned* vtu = smu + 2688;     // [16][60]
    float*    S   = (float*)(smu + 3648);  // [112][116]
    unsigned* SPu = smu + 16640;    // [112][60]

    int bh = blockIdx.x;
    size_t base = (size_t)bh * CC * HDIM;
    int tid = threadIdx.x;
    int lane = tid & 31, w = tid >> 5;
    int gr = lane >> 2, gc = lane & 3;

    int arow = (lane & 7) + ((lane >> 3) & 1) * 8;
    int acolw = (lane >> 4) * 4;
    int brow = (lane & 7) + ((lane >> 4) & 1) * 8;
    int bcolw = ((lane >> 3) & 1) * 4;

    // staging: sources already bf16 in target layouts -> uint4 copies
    const uint4* qsrc = (const uint4*)(g_q + base);
    const uint4* ksrc = (const uint4*)(g_k + base);
    const uint4* vsrc = (const uint4*)(g_v + base);
    {   // q,k: 112 rows x 2 uint4
        int i = tid;               // 0..223 == exactly 224 quads
        int s = i >> 1, h4 = i & 1;
        *(uint4*)(qsu + s * 12 + h4 * 4) = qsrc[i];
        *(uint4*)(ksu + s * 12 + h4 * 4) = ksrc[i];
        // v: 16 rows x 14 uint4 = 224 quads
        int hd = i / 14, sp = i % 14;
        *(uint4*)(vtu + hd * 60 + sp * 4) = vsrc[(size_t)hd * 14 + sp];
    }
    __syncthreads();

    // QK^T: A once (1 ldsm4), B: 7 ldsm4 covering 14 n-tiles
    {
        unsigned a[4];
        ldsm4(a, su(qsu + (w * 16 + arow) * 12 + acolw));
#pragma unroll
        for (int bj = 0; bj < 7; bj++) {
            unsigned b[4];
            ldsm4(b, su(ksu + (bj * 16 + brow) * 12 + bcolw));
#pragma unroll
            for (int nh = 0; nh < 2; nh++) {
                float c[4] = {};
                mma16(c, a, &b[nh * 2]);
                int col = (bj * 2 + nh) * 8 + 2 * gc;
                *(float2*)&S[(w * 16 + gr) * 116 + col]     = make_float2(c[0] * 0.25f, c[1] * 0.25f);
                *(float2*)&S[(w * 16 + gr + 8) * 116 + col] = make_float2(c[2] * 0.25f, c[3] * 0.25f);
            }
        }
    }
    __syncwarp();

    // softmax: warp per row, 16 rows; bf16 probs to SP
    __nv_bfloat16* SPh = (__nv_bfloat16*)SPu;
#pragma unroll
    for (int rr = 0; rr < 16; rr++) {
        int r = w * 16 + rr;
        const float* row = S + r * 116;
        float v0 = row[lane];
        float v1 = row[lane + 32];
        float v2 = row[lane + 64];
        float v3 = (lane < 16) ? row[lane + 96] : -INFINITY;
        float mx = fmaxf(fmaxf(v0, v1), fmaxf(v2, v3));
#pragma unroll
        for (int off = 16; off > 0; off >>= 1)
            mx = fmaxf(mx, __shfl_xor_sync(0xFFFFFFFFu, mx, off));
        float e0 = __expf(v0 - mx), e1 = __expf(v1 - mx);
        float e2 = __expf(v2 - mx), e3 = __expf(v3 - mx);
        float sum = e0 + e1 + e2 + e3;
#pragma unroll
        for (int off = 16; off > 0; off >>= 1)
            sum += __shfl_xor_sync(0xFFFFFFFFu, sum, off);
        float inv = 1.f / sum;
        __nv_bfloat16* sp = SPh + r * 120;
        sp[lane]      = __float2bfloat16(e0 * inv);
        sp[lane + 32] = __float2bfloat16(e1 * inv);
        sp[lane + 64] = __float2bfloat16(e2 * inv);
        if (lane < 16) sp[lane + 96] = __float2bfloat16(e3 * inv);
    }
    __syncwarp();

    // PV: K=112 (7 k16 steps), N=16
    {
        float o[2][4] = {};
        unsigned apv = su(SPu + (w * 16 + arow) * 60 + acolw);
        unsigned bpv = su(vtu + brow * 60 + bcolw);
#pragma unroll
        for (int kw = 0; kw < 56; kw += 8) {
            unsigned a[4], b[4];
            ldsm4(a, apv + kw * 4);
            ldsm4(b, bpv + kw * 4);
            mma16(o[0], a, &b[0]);
            mma16(o[1], a, &b[2]);
        }
        int b_ = bh >> 3, h = bh & 7;
#pragma unroll
        for (int ni = 0; ni < 2; ni++) {
#pragma unroll
            for (int r2 = 0; r2 < 2; r2++) {
                int s = w * 16 + gr + r2 * 8;
                int hd = ni * 8 + 2 * gc;
                size_t dst = ((size_t)(b_ * CC) + s) * DD + h * HDIM + hd;
                *(__nv_bfloat162*)&g_attn[dst] =
                    __floats2bfloat162_rn(o[ni][2 * r2], o[ni][2 * r2 + 1]);
            }
        }
    }
}

// ---------------------------------------------------------------------------
// Kernel 4: output projection + bias + residual + LayerNorm.
// Block 128x128, 8 warps, warp tile 64x32. ldmatrix loads.
// ---------------------------------------------------------------------------
__global__ void __launch_bounds__(256) k_out(
        const float* __restrict__ wo, const float* __restrict__ bo,
        const float* __restrict__ lg, const float* __restrict__ lb,
        float* __restrict__ out) {
    extern __shared__ unsigned smu[];
    unsigned* Xsu = smu;             // [128][68]
    unsigned* Wsu = smu + 128 * 68;  // [128][68]

    int tid = threadIdx.x;
    int m0 = blockIdx.x * 128;
    int lane = tid & 31, warp = tid >> 5;
    int wm = warp >> 2, wn = warp & 3;
    int gr = lane >> 2, gc = lane & 3;

    // stage X (bf16 attn) + W (fp32 wo)
    const uint4* asrc = (const uint4*)g_attn;
#pragma unroll
    for (int i = 0; i < 8; i++) {
        int idx = tid + i * 256;
        int row = idx >> 4, q4 = idx & 15;
        *(uint4*)(Xsu + row * 68 + q4 * 4) = asrc[(size_t)(m0 + row) * 16 + q4];
    }
#pragma unroll
    for (int i = 0; i < 16; i++) {
        int idx = tid + i * 256;
        int row = idx >> 5, c4 = (idx & 31) * 4;
        float4 v = *(const float4*)(wo + row * DD + c4);
        Wsu[row * 68 + (c4 >> 1)]     = packbf(v.x, v.y);
        Wsu[row * 68 + (c4 >> 1) + 1] = packbf(v.z, v.w);
    }
    __syncthreads();

    int arow = (lane & 7) + ((lane >> 3) & 1) * 8;
    int acolw = (lane >> 4) * 4;
    int brow = (lane & 7) + ((lane >> 4) & 1) * 8;
    int bcolw = ((lane >> 3) & 1) * 4;

    unsigned abase[4], bbase[2];
#pragma unroll
    for (int mi = 0; mi < 4; mi++)
        abase[mi] = su(Xsu + (wm * 64 + mi * 16 + arow) * 68 + acolw);
#pragma unroll
    for (int bj = 0; bj < 2; bj++)
        bbase[bj] = su(Wsu + (wn * 32 + bj * 16 + brow) * 68 + bcolw);

    float c[4][4][4] = {};
#pragma unroll
    for (int kw = 0; kw < 64; kw += 8) {
        unsigned a[4][4], b[2][4];
#pragma unroll
        for (int mi = 0; mi < 4; mi++) ldsm4(a[mi], abase[mi] + kw * 4);
#pragma unroll
        for (int bj = 0; bj < 2; bj++) ldsm4(b[bj], bbase[bj] + kw * 4);
#pragma unroll
        for (int mi = 0; mi < 4; mi++)
#pragma unroll
            for (int ni = 0; ni < 4; ni++)
                mma16(c[mi][ni], a[mi], &b[ni >> 1][(ni & 1) * 2]);
    }
    __syncthreads();   // done with Xs/Ws; overlay ys

    float* ys = (float*)smu;        // [128][132] = 67584 B < 69632 B
#pragma unroll
    for (int mi = 0; mi < 4; mi++) {
#pragma unroll
        for (int ni = 0; ni < 4; ni++) {
#pragma unroll
            for (int r2 = 0; r2 < 2; r2++) {
                int row = wm * 64 + mi * 16 + gr + r2 * 8;
                int col = wn * 32 + ni * 8 + 2 * gc;
                int m = m0 + row;
                const float* srow = g_src + (size_t)m * DD;
                ys[row * 132 + col]     = c[mi][ni][2*r2]   + bo[col]   + srow[col];
                ys[row * 132 + col + 1] = c[mi][ni][2*r2+1] + bo[col+1] + srow[col+1];
            }
        }
    }
    __syncthreads();

    // LayerNorm: warp per row, 16 rows per warp
#pragma unroll
    for (int rr = 0; rr < 16; rr++) {
        int r = warp * 16 + rr;
        float4 v4 = *(const float4*)(ys + r * 132 + lane * 4);
        float vals[4] = {v4.x, v4.y, v4.z, v4.w};
        float s1 = vals[0] + vals[1] + vals[2] + vals[3];
        float s2 = vals[0]*vals[0] + vals[1]*vals[1] + vals[2]*vals[2] + vals[3]*vals[3];
#pragma unroll
        for (int off = 16; off > 0; off >>= 1) {
            s1 += __shfl_xor_sync(0xFFFFFFFFu, s1, off);
            s2 += __shfl_xor_sync(0xFFFFFFFFu, s2, off);
        }
        float mu = s1 * (1.f / 128.f);
        float var = s2 * (1.f / 128.f) - mu * mu;
        float inv = rsqrtf(var + 1e-5f);
        int m = m0 + r;
#pragma unroll
        for (int j = 0; j < 4; j++) {
            int cidx = lane * 4 + j;
            out[(size_t)m * DD + cidx] = (vals[j] - mu) * inv * lg[cidx] + lb[cidx];
        }
    }
}

// ---------------------------------------------------------------------------
extern "C" void kernel_launch(void* const* d_in, const int* in_sizes, int n_in,
                              void* d_out, int out_size) {
    const float* x   = (const float*)d_in[0];
    const float* cw  = (const float*)d_in[1];
    const float* cb  = (const float*)d_in[2];
    const float* bg  = (const float*)d_in[3];
    const float* bb_ = (const float*)d_in[4];
    const float* bm  = (const float*)d_in[5];
    const float* bvv = (const float*)d_in[6];
    const float* wq  = (const float*)d_in[7];
    const float* bq  = (const float*)d_in[8];
    const float* wk  = (const float*)d_in[9];
    const float* bk  = (const float*)d_in[10];
    const float* wv  = (const float*)d_in[11];
    const float* bv  = (const float*)d_in[12];
    const float* wo  = (const float*)d_in[13];
    const float* bo  = (const float*)d_in[14];
    const float* lg  = (const float*)d_in[15];
    const float* lb  = (const float*)d_in[16];
    float* out = (float*)d_out;

    const int QKV_SMEM  = 2 * 128 * 68 * 4;   // 69632
    const int ATTN_SMEM = 23360 * 4;          // 93440
    const int OUT_SMEM  = 2 * 128 * 68 * 4;   // 69632
    cudaFuncSetAttribute(k_qkv,  cudaFuncAttributeMaxDynamicSharedMemorySize, QKV_SMEM);
    cudaFuncSetAttribute(k_attn, cudaFuncAttributeMaxDynamicSharedMemorySize, ATTN_SMEM);
    cudaFuncSetAttribute(k_out,  cudaFuncAttributeMaxDynamicSharedMemorySize, OUT_SMEM);

    k_conv<<<MM, 128>>>(x, cw, cb, bg, bb_, bm, bvv);
    k_qkv<<<MM / 128, 256, QKV_SMEM>>>(wq, bq, wk, bk, wv, bv);
    k_attn<<<BB * HH, 224, ATTN_SMEM>>>();
    k_out<<<MM / 128, 256, OUT_SMEM>>>(wo, bo, lg, lb, out);
}

// round 5
// speedup vs baseline: 6.3996x; 1.6561x over previous
#include <cuda_runtime.h>
#include <cuda_bf16.h>
#include <cstdint>

#define BB 512
#define CC 112
#define DD 128
#define HH 8
#define HDIM 16
#define KW 8
#define MM (BB*CC)   // 57344

// Scratch (allocation-free contract)
__device__ float g_src[(size_t)MM * DD];                      // fp32 residual
__device__ __nv_bfloat16 g_srcb[(size_t)MM * DD];             // bf16 copy for GEMM A
__device__ __nv_bfloat16 g_wb[4 * DD * DD];                   // bf16 wq|wk|wv|wo
__device__ __nv_bfloat16 g_q[(size_t)BB * HH * CC * HDIM];    // [B,H,S,hd]
__device__ __nv_bfloat16 g_k[(size_t)BB * HH * CC * HDIM];    // [B,H,S,hd]
__device__ __nv_bfloat16 g_v[(size_t)BB * HH * HDIM * CC];    // [B,H,hd,S] transposed
__device__ __nv_bfloat16 g_attn[(size_t)MM * DD];             // [B,S,D]

__device__ __forceinline__ unsigned packbf(float a, float b) {
    __nv_bfloat162 p = __floats2bfloat162_rn(a, b);
    return *reinterpret_cast<unsigned*>(&p);
}
__device__ __forceinline__ void mma16(float* c, const unsigned* a, const unsigned* b) {
    asm volatile(
        "mma.sync.aligned.m16n8k16.row.col.f32.bf16.bf16.f32 "
        "{%0,%1,%2,%3}, {%4,%5,%6,%7}, {%8,%9}, {%0,%1,%2,%3};"
        : "+f"(c[0]), "+f"(c[1]), "+f"(c[2]), "+f"(c[3])
        : "r"(a[0]), "r"(a[1]), "r"(a[2]), "r"(a[3]), "r"(b[0]), "r"(b[1]));
}
__device__ __forceinline__ void ldsm4(unsigned* r, unsigned addr) {
    asm volatile("ldmatrix.sync.aligned.m8n8.x4.shared.b16 {%0,%1,%2,%3}, [%4];"
        : "=r"(r[0]), "=r"(r[1]), "=r"(r[2]), "=r"(r[3]) : "r"(addr));
}
__device__ __forceinline__ unsigned su(const void* p) {
    return (unsigned)__cvta_generic_to_shared(p);
}
__device__ __forceinline__ void cpa16(unsigned dst, const void* src) {
    asm volatile("cp.async.cg.shared.global [%0], [%1], 16;" :: "r"(dst), "l"(src));
}
#define CP_COMMIT() asm volatile("cp.async.commit_group;")
#define CP_WAIT0()  asm volatile("cp.async.wait_group 0;")

// ---------------------------------------------------------------------------
// Kernel 0: weights fp32 -> bf16 (wq|wk|wv|wo), run once per launch
// ---------------------------------------------------------------------------
__global__ void k_prep(const float* __restrict__ wq, const float* __restrict__ wk,
                       const float* __restrict__ wv, const float* __restrict__ wo) {
    int m = blockIdx.x >> 4;
    const float* s = (m == 0) ? wq : (m == 1) ? wk : (m == 2) ? wv : wo;
    int i = ((blockIdx.x & 15) * 256 + threadIdx.x) * 4;
    float4 v = *(const float4*)(s + i);
    uint2 p = {packbf(v.x, v.y), packbf(v.z, v.w)};
    *(uint2*)(g_wb + m * DD * DD + i) = p;
}

// ---------------------------------------------------------------------------
// Kernel 1: depthwise conv -> GELU -> BN -> residual; 8 rows/block, float4
// ---------------------------------------------------------------------------
__global__ void __launch_bounds__(256) k_conv(
        const float* __restrict__ x,
        const float* __restrict__ cw, const float* __restrict__ cb,
        const float* __restrict__ bg, const float* __restrict__ bbias,
        const float* __restrict__ bm, const float* __restrict__ bvv) {
    __shared__ float xs[8 * DD];
    int tid = threadIdx.x;
    int row = tid >> 5, col = (tid & 31) * 4;
    int gr = blockIdx.x * 8 + row;
    float4 v = *(const float4*)(x + (size_t)gr * DD + col);
    *(float4*)&xs[row * DD + col] = v;
    __syncthreads();

    int c = gr % CC;
    float w[KW];
#pragma unroll
    for (int k = 0; k < KW; k++) w[k] = cw[c * KW + k];
    float bias = cb[c];
    float bnsc = bg[c] * rsqrtf(bvv[c] + 1e-5f);
    float bnm = bm[c], bnb = bbias[c];

    float so[4];
#pragma unroll
    for (int j = 0; j < 4; j++) {
        int d = col + j;
        float acc = 0.f;
#pragma unroll
        for (int k = 0; k < KW; k++) {
            int idx = d - 3 + k;
            float xv = (idx >= 0 && idx < DD) ? xs[row * DD + idx] : 0.f;
            acc += xv * w[k];
        }
        acc += bias;
        float g = 0.5f * acc * (1.f + erff(acc * 0.70710678118654752f));
        float h = (g - bnm) * bnsc + bnb;
        so[j] = xs[row * DD + d] + h;
    }
    *(float4*)(g_src + (size_t)gr * DD + col) = make_float4(so[0], so[1], so[2], so[3]);
    uint2 p = {packbf(so[0], so[1]), packbf(so[2], so[3])};
    *(uint2*)(g_srcb + (size_t)gr * DD + col) = p;
}

// ---------------------------------------------------------------------------
// Kernel 2: QKV projection. Block = 128 rows x 384 cols, double-buffered
// weight staging overlapped with compute via cp.async.
// ---------------------------------------------------------------------------
__global__ void __launch_bounds__(256) k_qkv(
        const float* __restrict__ bq, const float* __restrict__ bk,
        const float* __restrict__ bvp) {
    extern __shared__ unsigned smu[];
    unsigned* Asu = smu;                 // [128][68]
    unsigned* Bbuf[2] = {smu + 128 * 68, smu + 2 * 128 * 68};

    int tid = threadIdx.x;
    int m0 = blockIdx.x * 128;
    int lane = tid & 31, warp = tid >> 5;
    int wm = warp >> 2, wn = warp & 3;
    int gr = lane >> 2, gc = lane & 3;

    // stage A (bf16 src) + B0 (wq) via cp.async
    const char* abase_g = (const char*)g_srcb + (size_t)m0 * 256;
    const char* wb0 = (const char*)g_wb;
#pragma unroll
    for (int i = 0; i < 8; i++) {
        int idx = tid + i * 256;
        int row = idx >> 4, q4 = idx & 15;
        cpa16(su(Asu + row * 68 + q4 * 4), abase_g + row * 256 + q4 * 16);
        cpa16(su(Bbuf[0] + row * 68 + q4 * 4), wb0 + row * 256 + q4 * 16);
    }
    CP_COMMIT(); CP_WAIT0();
    __syncthreads();

    int arow = (lane & 7) + ((lane >> 3) & 1) * 8;
    int acolw = (lane >> 4) * 4;
    int brow = (lane & 7) + ((lane >> 4) & 1) * 8;
    int bcolw = ((lane >> 3) & 1) * 4;

    unsigned abase[4];
#pragma unroll
    for (int mi = 0; mi < 4; mi++)
        abase[mi] = su(Asu + (wm * 64 + mi * 16 + arow) * 68 + acolw);

    for (int sel = 0; sel < 3; sel++) {
        // prefetch next weight matrix into the other buffer
        if (sel < 2) {
            const char* wbn = (const char*)g_wb + (size_t)(sel + 1) * DD * DD * 2;
            unsigned* dst = Bbuf[(sel + 1) & 1];
#pragma unroll
            for (int i = 0; i < 8; i++) {
                int idx = tid + i * 256;
                int row = idx >> 4, q4 = idx & 15;
                cpa16(su(dst + row * 68 + q4 * 4), wbn + row * 256 + q4 * 16);
            }
            CP_COMMIT();
        }

        unsigned* Bsu = Bbuf[sel & 1];
        unsigned bbase[2];
#pragma unroll
        for (int bj = 0; bj < 2; bj++)
            bbase[bj] = su(Bsu + (wn * 32 + bj * 16 + brow) * 68 + bcolw);

        float c[4][4][4] = {};
#pragma unroll
        for (int kw = 0; kw < 64; kw += 8) {
            unsigned a[4][4], b[2][4];
#pragma unroll
            for (int mi = 0; mi < 4; mi++) ldsm4(a[mi], abase[mi] + kw * 4);
#pragma unroll
            for (int bj = 0; bj < 2; bj++) ldsm4(b[bj], bbase[bj] + kw * 4);
#pragma unroll
            for (int mi = 0; mi < 4; mi++)
#pragma unroll
                for (int ni = 0; ni < 4; ni++)
                    mma16(c[mi][ni], a[mi], &b[ni >> 1][(ni & 1) * 2]);
        }

        const float* bias = (sel == 0) ? bq : (sel == 1) ? bk : bvp;
#pragma unroll
        for (int mi = 0; mi < 4; mi++) {
#pragma unroll
            for (int ni = 0; ni < 4; ni++) {
#pragma unroll
                for (int r2 = 0; r2 < 2; r2++) {
                    int row = wm * 64 + mi * 16 + gr + r2 * 8;
                    int col = wn * 32 + ni * 8 + 2 * gc;
                    int m = m0 + row;
                    int b_ = m / CC, s = m % CC;
                    int h = col >> 4, hd = col & 15;
                    float v0 = c[mi][ni][2 * r2]     + bias[col];
                    float v1 = c[mi][ni][2 * r2 + 1] + bias[col + 1];
                    if (sel == 0) {
                        size_t dst = ((size_t)(b_ * HH + h) * CC + s) * HDIM + hd;
                        *(__nv_bfloat162*)&g_q[dst] = __floats2bfloat162_rn(v0, v1);
                    } else if (sel == 1) {
                        size_t dst = ((size_t)(b_ * HH + h) * CC + s) * HDIM + hd;
                        *(__nv_bfloat162*)&g_k[dst] = __floats2bfloat162_rn(v0, v1);
                    } else {
                        size_t dstT = ((size_t)(b_ * HH + h) * HDIM + hd) * CC + s;
                        g_v[dstT]      = __float2bfloat16(v0);
                        g_v[dstT + CC] = __float2bfloat16(v1);
                    }
                }
            }
        }
        if (sel < 2) { CP_WAIT0(); __syncthreads(); }
    }
}

// ---------------------------------------------------------------------------
// Kernel 3: attention per (b,h). Register-resident softmax: scores never
// leave accumulator fragments; row stats via quad shfl_xor.
// ---------------------------------------------------------------------------
__global__ void __launch_bounds__(224) k_attn() {
    __shared__ unsigned qsu[112 * 12];
    __shared__ unsigned ksu[112 * 12];
    __shared__ unsigned vtu[16 * 60];

    int bh = blockIdx.x;
    size_t base2 = (size_t)bh * CC * HDIM * 2;   // byte offset
    int tid = threadIdx.x;
    int lane = tid & 31, w = tid >> 5;
    int gr = lane >> 2, gc = lane & 3;

    // cp.async staging: 1 16B chunk per thread per array
    {
        int i = tid;
        int s = i >> 1, h4 = i & 1;
        cpa16(su(qsu + s * 12 + h4 * 4), (const char*)g_q + base2 + i * 16);
        cpa16(su(ksu + s * 12 + h4 * 4), (const char*)g_k + base2 + i * 16);
        int hd = i / 14, sp = i % 14;
        cpa16(su(vtu + hd * 60 + sp * 4), (const char*)g_v + base2 + i * 16);
    }
    CP_COMMIT(); CP_WAIT0();
    __syncthreads();

    int arow = (lane & 7) + ((lane >> 3) & 1) * 8;
    int acolw = (lane >> 4) * 4;
    int brow = (lane & 7) + ((lane >> 4) & 1) * 8;
    int bcolw = ((lane >> 3) & 1) * 4;

    // QK^T into registers: s[14][4]
    float s[14][4] = {};
    {
        unsigned a[4];
        ldsm4(a, su(qsu + (w * 16 + arow) * 12 + acolw));
#pragma unroll
        for (int bj = 0; bj < 7; bj++) {
            unsigned b[4];
            ldsm4(b, su(ksu + (bj * 16 + brow) * 12 + bcolw));
            mma16(s[2 * bj],     a, &b[0]);
            mma16(s[2 * bj + 1], a, &b[2]);
        }
    }

    // scale + in-register softmax. Row gr: s[j][0..1]; row gr+8: s[j][2..3].
    float mx0 = -1e30f, mx1 = -1e30f;
#pragma unroll
    for (int j = 0; j < 14; j++) {
#pragma unroll
        for (int i = 0; i < 4; i++) s[j][i] *= 0.25f;
        mx0 = fmaxf(mx0, fmaxf(s[j][0], s[j][1]));
        mx1 = fmaxf(mx1, fmaxf(s[j][2], s[j][3]));
    }
    mx0 = fmaxf(mx0, __shfl_xor_sync(0xFFFFFFFFu, mx0, 1));
    mx0 = fmaxf(mx0, __shfl_xor_sync(0xFFFFFFFFu, mx0, 2));
    mx1 = fmaxf(mx1, __shfl_xor_sync(0xFFFFFFFFu, mx1, 1));
    mx1 = fmaxf(mx1, __shfl_xor_sync(0xFFFFFFFFu, mx1, 2));

    float sum0 = 0.f, sum1 = 0.f;
#pragma unroll
    for (int j = 0; j < 14; j++) {
        s[j][0] = __expf(s[j][0] - mx0);
        s[j][1] = __expf(s[j][1] - mx0);
        s[j][2] = __expf(s[j][2] - mx1);
        s[j][3] = __expf(s[j][3] - mx1);
        sum0 += s[j][0] + s[j][1];
        sum1 += s[j][2] + s[j][3];
    }
    sum0 += __shfl_xor_sync(0xFFFFFFFFu, sum0, 1);
    sum0 += __shfl_xor_sync(0xFFFFFFFFu, sum0, 2);
    sum1 += __shfl_xor_sync(0xFFFFFFFFu, sum1, 1);
    sum1 += __shfl_xor_sync(0xFFFFFFFFu, sum1, 2);
    float inv0 = 1.f / sum0, inv1 = 1.f / sum1;

    // pack P into A-fragments for PV
    unsigned ap[7][4];
#pragma unroll
    for (int t = 0; t < 7; t++) {
        ap[t][0] = packbf(s[2 * t][0] * inv0,     s[2 * t][1] * inv0);
        ap[t][1] = packbf(s[2 * t][2] * inv1,     s[2 * t][3] * inv1);
        ap[t][2] = packbf(s[2 * t + 1][0] * inv0, s[2 * t + 1][1] * inv0);
        ap[t][3] = packbf(s[2 * t + 1][2] * inv1, s[2 * t + 1][3] * inv1);
    }

    // PV: K=112 (7 k16 steps), N=16
    float o[2][4] = {};
    unsigned bpv = su(vtu + brow * 60 + bcolw);
#pragma unroll
    for (int t = 0; t < 7; t++) {
        unsigned b[4];
        ldsm4(b, bpv + t * 32);
        mma16(o[0], ap[t], &b[0]);
        mma16(o[1], ap[t], &b[2]);
    }
    int b_ = bh >> 3, h = bh & 7;
#pragma unroll
    for (int ni = 0; ni < 2; ni++) {
#pragma unroll
        for (int r2 = 0; r2 < 2; r2++) {
            int sq = w * 16 + gr + r2 * 8;
            int hd = ni * 8 + 2 * gc;
            size_t dst = ((size_t)(b_ * CC) + sq) * DD + h * HDIM + hd;
            *(__nv_bfloat162*)&g_attn[dst] =
                __floats2bfloat162_rn(o[ni][2 * r2], o[ni][2 * r2 + 1]);
        }
    }
}

// ---------------------------------------------------------------------------
// Kernel 4: output projection + bias + residual + LayerNorm.
// ---------------------------------------------------------------------------
__global__ void __launch_bounds__(256) k_out(
        const float* __restrict__ bo,
        const float* __restrict__ lg, const float* __restrict__ lb,
        float* __restrict__ out) {
    extern __shared__ unsigned smu[];
    unsigned* Xsu = smu;             // [128][68]
    unsigned* Wsu = smu + 128 * 68;  // [128][68]

    int tid = threadIdx.x;
    int m0 = blockIdx.x * 128;
    int lane = tid & 31, warp = tid >> 5;
    int wm = warp >> 2, wn = warp & 3;
    int gr = lane >> 2, gc = lane & 3;

    const char* xg = (const char*)g_attn + (size_t)m0 * 256;
    const char* wg = (const char*)g_wb + (size_t)3 * DD * DD * 2;
#pragma unroll
    for (int i = 0; i < 8; i++) {
        int idx = tid + i * 256;
        int row = idx >> 4, q4 = idx & 15;
        cpa16(su(Xsu + row * 68 + q4 * 4), xg + row * 256 + q4 * 16);
        cpa16(su(Wsu + row * 68 + q4 * 4), wg + row * 256 + q4 * 16);
    }
    CP_COMMIT(); CP_WAIT0();
    __syncthreads();

    int arow = (lane & 7) + ((lane >> 3) & 1) * 8;
    int acolw = (lane >> 4) * 4;
    int brow = (lane & 7) + ((lane >> 4) & 1) * 8;
    int bcolw = ((lane >> 3) & 1) * 4;

    unsigned abase[4], bbase[2];
#pragma unroll
    for (int mi = 0; mi < 4; mi++)
        abase[mi] = su(Xsu + (wm * 64 + mi * 16 + arow) * 68 + acolw);
#pragma unroll
    for (int bj = 0; bj < 2; bj++)
        bbase[bj] = su(Wsu + (wn * 32 + bj * 16 + brow) * 68 + bcolw);

    float c[4][4][4] = {};
#pragma unroll
    for (int kw = 0; kw < 64; kw += 8) {
        unsigned a[4][4], b[2][4];
#pragma unroll
        for (int mi = 0; mi < 4; mi++) ldsm4(a[mi], abase[mi] + kw * 4);
#pragma unroll
        for (int bj = 0; bj < 2; bj++) ldsm4(b[bj], bbase[bj] + kw * 4);
#pragma unroll
        for (int mi = 0; mi < 4; mi++)
#pragma unroll
            for (int ni = 0; ni < 4; ni++)
                mma16(c[mi][ni], a[mi], &b[ni >> 1][(ni & 1) * 2]);
    }
    __syncthreads();   // done with Xs/Ws; overlay ys

    float* ys = (float*)smu;        // [128][132]
#pragma unroll
    for (int mi = 0; mi < 4; mi++) {
#pragma unroll
        for (int ni = 0; ni < 4; ni++) {
#pragma unroll
            for (int r2 = 0; r2 < 2; r2++) {
                int row = wm * 64 + mi * 16 + gr + r2 * 8;
                int col = wn * 32 + ni * 8 + 2 * gc;
                int m = m0 + row;
                const float* srow = g_src + (size_t)m * DD;
                ys[row * 132 + col]     = c[mi][ni][2*r2]   + bo[col]   + srow[col];
                ys[row * 132 + col + 1] = c[mi][ni][2*r2+1] + bo[col+1] + srow[col+1];
            }
        }
    }
    __syncthreads();

#pragma unroll
    for (int rr = 0; rr < 16; rr++) {
        int r = warp * 16 + rr;
        float4 v4 = *(const float4*)(ys + r * 132 + lane * 4);
        float vals[4] = {v4.x, v4.y, v4.z, v4.w};
        float s1 = vals[0] + vals[1] + vals[2] + vals[3];
        float s2 = vals[0]*vals[0] + vals[1]*vals[1] + vals[2]*vals[2] + vals[3]*vals[3];
#pragma unroll
        for (int off = 16; off > 0; off >>= 1) {
            s1 += __shfl_xor_sync(0xFFFFFFFFu, s1, off);
            s2 += __shfl_xor_sync(0xFFFFFFFFu, s2, off);
        }
        float mu = s1 * (1.f / 128.f);
        float var = s2 * (1.f / 128.f) - mu * mu;
        float inv = rsqrtf(var + 1e-5f);
        int m = m0 + r;
#pragma unroll
        for (int j = 0; j < 4; j++) {
            int cidx = lane * 4 + j;
            out[(size_t)m * DD + cidx] = (vals[j] - mu) * inv * lg[cidx] + lb[cidx];
        }
    }
}

// ---------------------------------------------------------------------------
extern "C" void kernel_launch(void* const* d_in, const int* in_sizes, int n_in,
                              void* d_out, int out_size) {
    const float* x   = (const float*)d_in[0];
    const float* cw  = (const float*)d_in[1];
    const float* cb  = (const float*)d_in[2];
    const float* bg  = (const float*)d_in[3];
    const float* bb_ = (const float*)d_in[4];
    const float* bm  = (const float*)d_in[5];
    const float* bvv = (const float*)d_in[6];
    const float* wq  = (const float*)d_in[7];
    const float* bq  = (const float*)d_in[8];
    const float* wk  = (const float*)d_in[9];
    const float* bk  = (const float*)d_in[10];
    const float* wv  = (const float*)d_in[11];
    const float* bv  = (const float*)d_in[12];
    const float* wo  = (const float*)d_in[13];
    const float* bo  = (const float*)d_in[14];
    const float* lg  = (const float*)d_in[15];
    const float* lb  = (const float*)d_in[16];
    float* out = (float*)d_out;

    const int QKV_SMEM = 3 * 128 * 68 * 4;   // 104448
    const int OUT_SMEM = 2 * 128 * 68 * 4;   // 69632
    cudaFuncSetAttribute(k_qkv, cudaFuncAttributeMaxDynamicSharedMemorySize, QKV_SMEM);
    cudaFuncSetAttribute(k_out, cudaFuncAttributeMaxDynamicSharedMemorySize, OUT_SMEM);

    k_prep<<<64, 256>>>(wq, wk, wv, wo);
    k_conv<<<MM / 8, 256>>>(x, cw, cb, bg, bb_, bm, bvv);
    k_qkv<<<MM / 128, 256, QKV_SMEM>>>(bq, bk, bv);
    k_attn<<<BB * HH, 224>>>();
    k_out<<<MM / 128, 256, OUT_SMEM>>>(bo, lg, lb, out);
}

// round 6
// speedup vs baseline: 6.8175x; 1.0653x over previous
#include <cuda_runtime.h>
#include <cuda_bf16.h>
#include <cstdint>

#define BB 512
#define CC 112
#define DD 128
#define HH 8
#define HDIM 16
#define KW 8
#define MM (BB*CC)   // 57344

// Scratch (allocation-free contract)
__device__ float g_src[(size_t)MM * DD];                      // fp32 residual
__device__ __nv_bfloat16 g_srcb[(size_t)MM * DD];             // bf16 copy for GEMM A
__device__ __nv_bfloat16 g_wb[4 * DD * DD];                   // bf16 wq|wk|wv|wo
__device__ __nv_bfloat16 g_q[(size_t)BB * HH * CC * HDIM];    // [B,H,S,hd]
__device__ __nv_bfloat16 g_k[(size_t)BB * HH * CC * HDIM];    // [B,H,S,hd]
__device__ __nv_bfloat16 g_v[(size_t)BB * HH * HDIM * CC];    // [B,H,hd,S] transposed
__device__ __nv_bfloat16 g_attn[(size_t)MM * DD];             // [B,S,D]

__device__ __forceinline__ unsigned packbf(float a, float b) {
    __nv_bfloat162 p = __floats2bfloat162_rn(a, b);
    return *reinterpret_cast<unsigned*>(&p);
}
__device__ __forceinline__ float ex2(float x) {
    float r;
    asm("ex2.approx.f32 %0, %1;" : "=f"(r) : "f"(x));
    return r;
}
__device__ __forceinline__ void mma16(float* c, const unsigned* a, const unsigned* b) {
    asm volatile(
        "mma.sync.aligned.m16n8k16.row.col.f32.bf16.bf16.f32 "
        "{%0,%1,%2,%3}, {%4,%5,%6,%7}, {%8,%9}, {%0,%1,%2,%3};"
        : "+f"(c[0]), "+f"(c[1]), "+f"(c[2]), "+f"(c[3])
        : "r"(a[0]), "r"(a[1]), "r"(a[2]), "r"(a[3]), "r"(b[0]), "r"(b[1]));
}
__device__ __forceinline__ void ldsm4(unsigned* r, unsigned addr) {
    asm volatile("ldmatrix.sync.aligned.m8n8.x4.shared.b16 {%0,%1,%2,%3}, [%4];"
        : "=r"(r[0]), "=r"(r[1]), "=r"(r[2]), "=r"(r[3]) : "r"(addr));
}
__device__ __forceinline__ unsigned su(const void* p) {
    return (unsigned)__cvta_generic_to_shared(p);
}
__device__ __forceinline__ void cpa16(unsigned dst, const void* src) {
    asm volatile("cp.async.cg.shared.global [%0], [%1], 16;" :: "r"(dst), "l"(src));
}
#define CP_COMMIT() asm volatile("cp.async.commit_group;")
#define CP_WAIT0()  asm volatile("cp.async.wait_group 0;")

// ---------------------------------------------------------------------------
// Kernel 0: weights fp32 -> bf16 (wq|wk|wv|wo)
// ---------------------------------------------------------------------------
__global__ void k_prep(const float* __restrict__ wq, const float* __restrict__ wk,
                       const float* __restrict__ wv, const float* __restrict__ wo) {
    int m = blockIdx.x >> 4;
    const float* s = (m == 0) ? wq : (m == 1) ? wk : (m == 2) ? wv : wo;
    int i = ((blockIdx.x & 15) * 256 + threadIdx.x) * 4;
    float4 v = *(const float4*)(s + i);
    uint2 p = {packbf(v.x, v.y), packbf(v.z, v.w)};
    *(uint2*)(g_wb + m * DD * DD + i) = p;
}

// ---------------------------------------------------------------------------
// Kernel 1: depthwise conv -> GELU -> BN -> residual; 8 rows/block, float4
// ---------------------------------------------------------------------------
__global__ void __launch_bounds__(256) k_conv(
        const float* __restrict__ x,
        const float* __restrict__ cw, const float* __restrict__ cb,
        const float* __restrict__ bg, const float* __restrict__ bbias,
        const float* __restrict__ bm, const float* __restrict__ bvv) {
    __shared__ float xs[8 * DD];
    int tid = threadIdx.x;
    int row = tid >> 5, col = (tid & 31) * 4;
    int gr = blockIdx.x * 8 + row;
    float4 v = *(const float4*)(x + (size_t)gr * DD + col);
    *(float4*)&xs[row * DD + col] = v;
    __syncthreads();

    int c = gr % CC;
    float w[KW];
#pragma unroll
    for (int k = 0; k < KW; k++) w[k] = cw[c * KW + k];
    float bias = cb[c];
    float bnsc = bg[c] * rsqrtf(bvv[c] + 1e-5f);
    float bnm = bm[c], bnb = bbias[c];

    float so[4];
#pragma unroll
    for (int j = 0; j < 4; j++) {
        int d = col + j;
        float acc = 0.f;
#pragma unroll
        for (int k = 0; k < KW; k++) {
            int idx = d - 3 + k;
            float xv = (idx >= 0 && idx < DD) ? xs[row * DD + idx] : 0.f;
            acc += xv * w[k];
        }
        acc += bias;
        float g = 0.5f * acc * (1.f + erff(acc * 0.70710678118654752f));
        float h = (g - bnm) * bnsc + bnb;
        so[j] = xs[row * DD + d] + h;
    }
    *(float4*)(g_src + (size_t)gr * DD + col) = make_float4(so[0], so[1], so[2], so[3]);
    uint2 p = {packbf(so[0], so[1]), packbf(so[2], so[3])};
    *(uint2*)(g_srcb + (size_t)gr * DD + col) = p;
}

// ---------------------------------------------------------------------------
// Kernel 2: QKV projection. Block = 128 rows x 384 cols, double-buffered
// weight staging overlapped with compute via cp.async.
// ---------------------------------------------------------------------------
__global__ void __launch_bounds__(256) k_qkv(
        const float* __restrict__ bq, const float* __restrict__ bk,
        const float* __restrict__ bvp) {
    extern __shared__ unsigned smu[];
    unsigned* Asu = smu;                 // [128][68]
    unsigned* Bbuf[2] = {smu + 128 * 68, smu + 2 * 128 * 68};

    int tid = threadIdx.x;
    int m0 = blockIdx.x * 128;
    int lane = tid & 31, warp = tid >> 5;
    int wm = warp >> 2, wn = warp & 3;
    int gr = lane >> 2, gc = lane & 3;

    const char* abase_g = (const char*)g_srcb + (size_t)m0 * 256;
    const char* wb0 = (const char*)g_wb;
#pragma unroll
    for (int i = 0; i < 8; i++) {
        int idx = tid + i * 256;
        int row = idx >> 4, q4 = idx & 15;
        cpa16(su(Asu + row * 68 + q4 * 4), abase_g + row * 256 + q4 * 16);
        cpa16(su(Bbuf[0] + row * 68 + q4 * 4), wb0 + row * 256 + q4 * 16);
    }
    CP_COMMIT(); CP_WAIT0();
    __syncthreads();

    int arow = (lane & 7) + ((lane >> 3) & 1) * 8;
    int acolw = (lane >> 4) * 4;
    int brow = (lane & 7) + ((lane >> 4) & 1) * 8;
    int bcolw = ((lane >> 3) & 1) * 4;

    unsigned abase[4];
#pragma unroll
    for (int mi = 0; mi < 4; mi++)
        abase[mi] = su(Asu + (wm * 64 + mi * 16 + arow) * 68 + acolw);

    for (int sel = 0; sel < 3; sel++) {
        if (sel < 2) {
            const char* wbn = (const char*)g_wb + (size_t)(sel + 1) * DD * DD * 2;
            unsigned* dst = Bbuf[(sel + 1) & 1];
#pragma unroll
            for (int i = 0; i < 8; i++) {
                int idx = tid + i * 256;
                int row = idx >> 4, q4 = idx & 15;
                cpa16(su(dst + row * 68 + q4 * 4), wbn + row * 256 + q4 * 16);
            }
            CP_COMMIT();
        }

        unsigned* Bsu = Bbuf[sel & 1];
        unsigned bbase[2];
#pragma unroll
        for (int bj = 0; bj < 2; bj++)
            bbase[bj] = su(Bsu + (wn * 32 + bj * 16 + brow) * 68 + bcolw);

        float c[4][4][4] = {};
#pragma unroll
        for (int kw = 0; kw < 64; kw += 8) {
            unsigned a[4][4], b[2][4];
#pragma unroll
            for (int mi = 0; mi < 4; mi++) ldsm4(a[mi], abase[mi] + kw * 4);
#pragma unroll
            for (int bj = 0; bj < 2; bj++) ldsm4(b[bj], bbase[bj] + kw * 4);
#pragma unroll
            for (int mi = 0; mi < 4; mi++)
#pragma unroll
                for (int ni = 0; ni < 4; ni++)
                    mma16(c[mi][ni], a[mi], &b[ni >> 1][(ni & 1) * 2]);
        }

        const float* bias = (sel == 0) ? bq : (sel == 1) ? bk : bvp;
#pragma unroll
        for (int mi = 0; mi < 4; mi++) {
#pragma unroll
            for (int ni = 0; ni < 4; ni++) {
#pragma unroll
                for (int r2 = 0; r2 < 2; r2++) {
                    int row = wm * 64 + mi * 16 + gr + r2 * 8;
                    int col = wn * 32 + ni * 8 + 2 * gc;
                    int m = m0 + row;
                    int b_ = m / CC, s = m % CC;
                    int h = col >> 4, hd = col & 15;
                    float v0 = c[mi][ni][2 * r2]     + bias[col];
                    float v1 = c[mi][ni][2 * r2 + 1] + bias[col + 1];
                    if (sel == 0) {
                        size_t dst = ((size_t)(b_ * HH + h) * CC + s) * HDIM + hd;
                        *(__nv_bfloat162*)&g_q[dst] = __floats2bfloat162_rn(v0, v1);
                    } else if (sel == 1) {
                        size_t dst = ((size_t)(b_ * HH + h) * CC + s) * HDIM + hd;
                        *(__nv_bfloat162*)&g_k[dst] = __floats2bfloat162_rn(v0, v1);
                    } else {
                        size_t dstT = ((size_t)(b_ * HH + h) * HDIM + hd) * CC + s;
                        g_v[dstT]      = __float2bfloat16(v0);
                        g_v[dstT + CC] = __float2bfloat16(v1);
                    }
                }
            }
        }
        if (sel < 2) { CP_WAIT0(); __syncthreads(); }
    }
}

// ---------------------------------------------------------------------------
// Kernel 3: attention per (b,h). No-max softmax (scores bounded ~|2|),
// exp2-folded scale, normalization deferred past PV.
// ---------------------------------------------------------------------------
__global__ void __launch_bounds__(224, 4) k_attn() {
    __shared__ unsigned qsu[112 * 12];
    __shared__ unsigned ksu[112 * 12];
    __shared__ unsigned vtu[16 * 60];

    int bh = blockIdx.x;
    size_t base2 = (size_t)bh * CC * HDIM * 2;   // byte offset
    int tid = threadIdx.x;
    int lane = tid & 31, w = tid >> 5;
    int gr = lane >> 2, gc = lane & 3;

    {
        int i = tid;
        int s = i >> 1, h4 = i & 1;
        cpa16(su(qsu + s * 12 + h4 * 4), (const char*)g_q + base2 + i * 16);
        cpa16(su(ksu + s * 12 + h4 * 4), (const char*)g_k + base2 + i * 16);
        int hd = i / 14, sp = i % 14;
        cpa16(su(vtu + hd * 60 + sp * 4), (const char*)g_v + base2 + i * 16);
    }
    CP_COMMIT(); CP_WAIT0();
    __syncthreads();

    int arow = (lane & 7) + ((lane >> 3) & 1) * 8;
    int acolw = (lane >> 4) * 4;
    int brow = (lane & 7) + ((lane >> 4) & 1) * 8;
    int bcolw = ((lane >> 3) & 1) * 4;

    // QK^T into registers: s[14][4]
    float s[14][4] = {};
    {
        unsigned a[4];
        ldsm4(a, su(qsu + (w * 16 + arow) * 12 + acolw));
#pragma unroll
        for (int bj = 0; bj < 7; bj++) {
            unsigned b[4];
            ldsm4(b, su(ksu + (bj * 16 + brow) * 12 + bcolw));
            mma16(s[2 * bj],     a, &b[0]);
            mma16(s[2 * bj + 1], a, &b[2]);
        }
    }

    // exp2(scale*log2e * s), no max-sub (|scores| ~ O(2)); pack unnormalized
    const float C = 0.25f * 1.44269504088896f;
    float sum0 = 0.f, sum1 = 0.f;
    unsigned ap[7][4];
#pragma unroll
    for (int t = 0; t < 7; t++) {
        float e00 = ex2(s[2 * t][0] * C),     e01 = ex2(s[2 * t][1] * C);
        float e02 = ex2(s[2 * t][2] * C),     e03 = ex2(s[2 * t][3] * C);
        float e10 = ex2(s[2 * t + 1][0] * C), e11 = ex2(s[2 * t + 1][1] * C);
        float e12 = ex2(s[2 * t + 1][2] * C), e13 = ex2(s[2 * t + 1][3] * C);
        sum0 += (e00 + e01) + (e10 + e11);
        sum1 += (e02 + e03) + (e12 + e13);
        ap[t][0] = packbf(e00, e01);
        ap[t][1] = packbf(e02, e03);
        ap[t][2] = packbf(e10, e11);
        ap[t][3] = packbf(e12, e13);
    }
    sum0 += __shfl_xor_sync(0xFFFFFFFFu, sum0, 1);
    sum0 += __shfl_xor_sync(0xFFFFFFFFu, sum0, 2);
    sum1 += __shfl_xor_sync(0xFFFFFFFFu, sum1, 1);
    sum1 += __shfl_xor_sync(0xFFFFFFFFu, sum1, 2);
    float inv0 = 1.f / sum0, inv1 = 1.f / sum1;

    // PV on unnormalized P; normalize outputs afterward
    float o[2][4] = {};
    unsigned bpv = su(vtu + brow * 60 + bcolw);
#pragma unroll
    for (int t = 0; t < 7; t++) {
        unsigned b[4];
        ldsm4(b, bpv + t * 32);
        mma16(o[0], ap[t], &b[0]);
        mma16(o[1], ap[t], &b[2]);
    }
    int b_ = bh >> 3, h = bh & 7;
#pragma unroll
    for (int ni = 0; ni < 2; ni++) {
        o[ni][0] *= inv0; o[ni][1] *= inv0;
        o[ni][2] *= inv1; o[ni][3] *= inv1;
#pragma unroll
        for (int r2 = 0; r2 < 2; r2++) {
            int sq = w * 16 + gr + r2 * 8;
            int hd = ni * 8 + 2 * gc;
            size_t dst = ((size_t)(b_ * CC) + sq) * DD + h * HDIM + hd;
            *(__nv_bfloat162*)&g_attn[dst] =
                __floats2bfloat162_rn(o[ni][2 * r2], o[ni][2 * r2 + 1]);
        }
    }
}

// ---------------------------------------------------------------------------
// Kernel 4: output projection + bias + residual + LayerNorm.
// ---------------------------------------------------------------------------
__global__ void __launch_bounds__(256) k_out(
        const float* __restrict__ bo,
        const float* __restrict__ lg, const float* __restrict__ lb,
        float* __restrict__ out) {
    extern __shared__ unsigned smu[];
    unsigned* Xsu = smu;             // [128][68]
    unsigned* Wsu = smu + 128 * 68;  // [128][68]

    int tid = threadIdx.x;
    int m0 = blockIdx.x * 128;
    int lane = tid & 31, warp = tid >> 5;
    int wm = warp >> 2, wn = warp & 3;
    int gr = lane >> 2, gc = lane & 3;

    const char* xg = (const char*)g_attn + (size_t)m0 * 256;
    const char* wg = (const char*)g_wb + (size_t)3 * DD * DD * 2;
#pragma unroll
    for (int i = 0; i < 8; i++) {
        int idx = tid + i * 256;
        int row = idx >> 4, q4 = idx & 15;
        cpa16(su(Xsu + row * 68 + q4 * 4), xg + row * 256 + q4 * 16);
        cpa16(su(Wsu + row * 68 + q4 * 4), wg + row * 256 + q4 * 16);
    }
    CP_COMMIT(); CP_WAIT0();
    __syncthreads();

    int arow = (lane & 7) + ((lane >> 3) & 1) * 8;
    int acolw = (lane >> 4) * 4;
    int brow = (lane & 7) + ((lane >> 4) & 1) * 8;
    int bcolw = ((lane >> 3) & 1) * 4;

    unsigned abase[4], bbase[2];
#pragma unroll
    for (int mi = 0; mi < 4; mi++)
        abase[mi] = su(Xsu + (wm * 64 + mi * 16 + arow) * 68 + acolw);
#pragma unroll
    for (int bj = 0; bj < 2; bj++)
        bbase[bj] = su(Wsu + (wn * 32 + bj * 16 + brow) * 68 + bcolw);

    float c[4][4][4] = {};
#pragma unroll
    for (int kw = 0; kw < 64; kw += 8) {
        unsigned a[4][4], b[2][4];
#pragma unroll
        for (int mi = 0; mi < 4; mi++) ldsm4(a[mi], abase[mi] + kw * 4);
#pragma unroll
        for (int bj = 0; bj < 2; bj++) ldsm4(b[bj], bbase[bj] + kw * 4);
#pragma unroll
        for (int mi = 0; mi < 4; mi++)
#pragma unroll
            for (int ni = 0; ni < 4; ni++)
                mma16(c[mi][ni], a[mi], &b[ni >> 1][(ni & 1) * 2]);
    }
    __syncthreads();   // done with Xs/Ws; overlay ys

    float* ys = (float*)smu;        // [128][132]
#pragma unroll
    for (int mi = 0; mi < 4; mi++) {
#pragma unroll
        for (int ni = 0; ni < 4; ni++) {
#pragma unroll
            for (int r2 = 0; r2 < 2; r2++) {
                int row = wm * 64 + mi * 16 + gr + r2 * 8;
                int col = wn * 32 + ni * 8 + 2 * gc;
                int m = m0 + row;
                const float* srow = g_src + (size_t)m * DD;
                ys[row * 132 + col]     = c[mi][ni][2*r2]   + bo[col]   + srow[col];
                ys[row * 132 + col + 1] = c[mi][ni][2*r2+1] + bo[col+1] + srow[col+1];
            }
        }
    }
    __syncthreads();

#pragma unroll
    for (int rr = 0; rr < 16; rr++) {
        int r = warp * 16 + rr;
        float4 v4 = *(const float4*)(ys + r * 132 + lane * 4);
        float vals[4] = {v4.x, v4.y, v4.z, v4.w};
        float s1 = vals[0] + vals[1] + vals[2] + vals[3];
        float s2 = vals[0]*vals[0] + vals[1]*vals[1] + vals[2]*vals[2] + vals[3]*vals[3];
#pragma unroll
        for (int off = 16; off > 0; off >>= 1) {
            s1 += __shfl_xor_sync(0xFFFFFFFFu, s1, off);
            s2 += __shfl_xor_sync(0xFFFFFFFFu, s2, off);
        }
        float mu = s1 * (1.f / 128.f);
        float var = s2 * (1.f / 128.f) - mu * mu;
        float inv = rsqrtf(var + 1e-5f);
        int m = m0 + r;
#pragma unroll
        for (int j = 0; j < 4; j++) {
            int cidx = lane * 4 + j;
            out[(size_t)m * DD + cidx] = (vals[j] - mu) * inv * lg[cidx] + lb[cidx];
        }
    }
}

// ---------------------------------------------------------------------------
extern "C" void kernel_launch(void* const* d_in, const int* in_sizes, int n_in,
                              void* d_out, int out_size) {
    const float* x   = (const float*)d_in[0];
    const float* cw  = (const float*)d_in[1];
    const float* cb  = (const float*)d_in[2];
    const float* bg  = (const float*)d_in[3];
    const float* bb_ = (const float*)d_in[4];
    const float* bm  = (const float*)d_in[5];
    const float* bvv = (const float*)d_in[6];
    const float* wq  = (const float*)d_in[7];
    const float* bq  = (const float*)d_in[8];
    const float* wk  = (const float*)d_in[9];
    const float* bk  = (const float*)d_in[10];
    const float* wv  = (const float*)d_in[11];
    const float* bv  = (const float*)d_in[12];
    const float* wo  = (const float*)d_in[13];
    const float* bo  = (const float*)d_in[14];
    const float* lg  = (const float*)d_in[15];
    const float* lb  = (const float*)d_in[16];
    float* out = (float*)d_out;

    const int QKV_SMEM = 3 * 128 * 68 * 4;   // 104448
    const int OUT_SMEM = 2 * 128 * 68 * 4;   // 69632
    cudaFuncSetAttribute(k_qkv, cudaFuncAttributeMaxDynamicSharedMemorySize, QKV_SMEM);
    cudaFuncSetAttribute(k_out, cudaFuncAttributeMaxDynamicSharedMemorySize, OUT_SMEM);

    k_prep<<<64, 256>>>(wq, wk, wv, wo);
    k_conv<<<MM / 8, 256>>>(x, cw, cb, bg, bb_, bm, bvv);
    k_qkv<<<MM / 128, 256, QKV_SMEM>>>(bq, bk, bv);
    k_attn<<<BB * HH, 224>>>();
    k_out<<<MM / 128, 256, OUT_SMEM>>>(bo, lg, lb, out);
}

// round 7
// speedup vs baseline: 7.1024x; 1.0418x over previous
#include <cuda_runtime.h>
#include <cuda_bf16.h>
#include <cstdint>

#define BB 512
#define CC 112
#define DD 128
#define HH 8
#define HDIM 16
#define KW 8
#define MM (BB*CC)   // 57344
#define NT 512

// Scratch (allocation-free contract)
__device__ float g_src[(size_t)MM * DD];           // fp32 residual
__device__ __nv_bfloat16 g_srcb[(size_t)MM * DD];  // bf16 copy for GEMM A
__device__ __nv_bfloat16 g_wb[4 * DD * DD];        // bf16 wq|wk|wv|wo

__device__ __forceinline__ unsigned packbf(float a, float b) {
    __nv_bfloat162 p = __floats2bfloat162_rn(a, b);
    return *reinterpret_cast<unsigned*>(&p);
}
__device__ __forceinline__ float ex2(float x) {
    float r;
    asm("ex2.approx.f32 %0, %1;" : "=f"(r) : "f"(x));
    return r;
}
__device__ __forceinline__ void mma16(float* c, const unsigned* a, const unsigned* b) {
    asm volatile(
        "mma.sync.aligned.m16n8k16.row.col.f32.bf16.bf16.f32 "
        "{%0,%1,%2,%3}, {%4,%5,%6,%7}, {%8,%9}, {%0,%1,%2,%3};"
        : "+f"(c[0]), "+f"(c[1]), "+f"(c[2]), "+f"(c[3])
        : "r"(a[0]), "r"(a[1]), "r"(a[2]), "r"(a[3]), "r"(b[0]), "r"(b[1]));
}
__device__ __forceinline__ void ldsm4(unsigned* r, unsigned addr) {
    asm volatile("ldmatrix.sync.aligned.m8n8.x4.shared.b16 {%0,%1,%2,%3}, [%4];"
        : "=r"(r[0]), "=r"(r[1]), "=r"(r[2]), "=r"(r[3]) : "r"(addr));
}
__device__ __forceinline__ unsigned su(const void* p) {
    return (unsigned)__cvta_generic_to_shared(p);
}
__device__ __forceinline__ void cpa16(unsigned dst, const void* src) {
    asm volatile("cp.async.cg.shared.global [%0], [%1], 16;" :: "r"(dst), "l"(src));
}
#define CP_COMMIT() asm volatile("cp.async.commit_group;")
#define CP_WAIT0()  asm volatile("cp.async.wait_group 0;")

// ---------------------------------------------------------------------------
// Kernel 0: weights fp32 -> bf16 (wq|wk|wv|wo)
// ---------------------------------------------------------------------------
__global__ void k_prep(const float* __restrict__ wq, const float* __restrict__ wk,
                       const float* __restrict__ wv, const float* __restrict__ wo) {
    int m = blockIdx.x >> 4;
    const float* s = (m == 0) ? wq : (m == 1) ? wk : (m == 2) ? wv : wo;
    int i = ((blockIdx.x & 15) * 256 + threadIdx.x) * 4;
    float4 v = *(const float4*)(s + i);
    uint2 p = {packbf(v.x, v.y), packbf(v.z, v.w)};
    *(uint2*)(g_wb + m * DD * DD + i) = p;
}

// ---------------------------------------------------------------------------
// Kernel 1: depthwise conv -> GELU -> BN -> residual; 8 rows/block, float4
// ---------------------------------------------------------------------------
__global__ void __launch_bounds__(256) k_conv(
        const float* __restrict__ x,
        const float* __restrict__ cw, const float* __restrict__ cb,
        const float* __restrict__ bg, const float* __restrict__ bbias,
        const float* __restrict__ bm, const float* __restrict__ bvv) {
    __shared__ float xs[8 * DD];
    int tid = threadIdx.x;
    int row = tid >> 5, col = (tid & 31) * 4;
    int gr = blockIdx.x * 8 + row;
    float4 v = *(const float4*)(x + (size_t)gr * DD + col);
    *(float4*)&xs[row * DD + col] = v;
    __syncthreads();

    int c = gr % CC;
    float w[KW];
#pragma unroll
    for (int k = 0; k < KW; k++) w[k] = cw[c * KW + k];
    float bias = cb[c];
    float bnsc = bg[c] * rsqrtf(bvv[c] + 1e-5f);
    float bnm = bm[c], bnb = bbias[c];

    float so[4];
#pragma unroll
    for (int j = 0; j < 4; j++) {
        int d = col + j;
        float acc = 0.f;
#pragma unroll
        for (int k = 0; k < KW; k++) {
            int idx = d - 3 + k;
            float xv = (idx >= 0 && idx < DD) ? xs[row * DD + idx] : 0.f;
            acc += xv * w[k];
        }
        acc += bias;
        float g = 0.5f * acc * (1.f + erff(acc * 0.70710678118654752f));
        float h = (g - bnm) * bnsc + bnb;
        so[j] = xs[row * DD + d] + h;
    }
    *(float4*)(g_src + (size_t)gr * DD + col) = make_float4(so[0], so[1], so[2], so[3]);
    uint2 p = {packbf(so[0], so[1]), packbf(so[2], so[3])};
    *(uint2*)(g_srcb + (size_t)gr * DD + col) = p;
}

// ---------------------------------------------------------------------------
// Kernel 2 (MEGAFUSED): per-batch block does QKV GEMM -> 8-head attention ->
// output projection -> residual -> LayerNorm. 512 threads, 196KB smem.
//
// smem word map:
//   [0     , 8704 )  Asu  : src A [128][68]; reused as Xs (attn out) later
//   [8704  , 17408)  B0   : weight buf [128][68]
//   [17408 , 26112)  B1   : weight buf [128][68]
//   [26112 , 33728)  qall : Q [112][68]
//   [33728 , 41344)  kall : K [112][68]
//   [41344 , 49024)  vt   : V^T [128hd][60 swords]
//   ys overlay (post-outproj): fp32 [128][132] at word 0 (spans Asu+B0)
// ---------------------------------------------------------------------------
__global__ void __launch_bounds__(NT) k_fused(
        const float* __restrict__ bq, const float* __restrict__ bk,
        const float* __restrict__ bvp, const float* __restrict__ bo,
        const float* __restrict__ lg, const float* __restrict__ lb,
        float* __restrict__ out) {
    extern __shared__ unsigned smu[];
    unsigned* Asu  = smu;
    unsigned* B0   = smu + 8704;
    unsigned* B1   = smu + 17408;
    unsigned* qall = smu + 26112;
    unsigned* kall = smu + 33728;
    unsigned* vt   = smu + 41344;

    int tid = threadIdx.x;
    int b = blockIdx.x;
    int lane = tid & 31, warp = tid >> 5;
    int wm = warp >> 2, wn = warp & 3;
    int gr = lane >> 2, gc = lane & 3;

    int arow = (lane & 7) + ((lane >> 3) & 1) * 8;
    int acolw = (lane >> 4) * 4;
    int brow = (lane & 7) + ((lane >> 4) & 1) * 8;
    int bcolw = ((lane >> 3) & 1) * 4;

    // ---- stage A (112 src rows, bf16) + zero-pad rows 112..127 + B0 = wq
    const char* ag = (const char*)g_srcb + (size_t)b * CC * 256;
#pragma unroll
    for (int i = tid; i < 1792; i += NT) {
        int row = i >> 4, q4 = i & 15;
        cpa16(su(Asu + row * 68 + q4 * 4), ag + i * 16);
    }
#pragma unroll
    for (int i = tid; i < 1088; i += NT) Asu[112 * 68 + i] = 0;
    {
        const char* wg = (const char*)g_wb;
#pragma unroll
        for (int i = tid; i < 2048; i += NT) {
            int row = i >> 4, q4 = i & 15;
            cpa16(su(B0 + row * 68 + q4 * 4), wg + i * 16);
        }
    }
    CP_COMMIT(); CP_WAIT0();
    __syncthreads();

    unsigned abase[2];
    abase[0] = su(Asu + (wm * 32 + arow) * 68 + acolw);
    abase[1] = su(Asu + (wm * 32 + 16 + arow) * 68 + acolw);

    // ================= QKV GEMMs =================
    for (int sel = 0; sel < 3; sel++) {
        {   // prefetch next weight matrix (wk, wv, then wo)
            const char* nw = (const char*)g_wb + (size_t)((sel < 2) ? sel + 1 : 3) * 32768;
            unsigned* dstb = (sel == 1) ? B0 : B1;   // sel0->B1, sel1->B0, sel2->B1
#pragma unroll
            for (int i = tid; i < 2048; i += NT) {
                int row = i >> 4, q4 = i & 15;
                cpa16(su(dstb + row * 68 + q4 * 4), nw + i * 16);
            }
            CP_COMMIT();
        }
        unsigned* Bsu = (sel & 1) ? B1 : B0;
        unsigned bbase[2];
        bbase[0] = su(Bsu + (wn * 32 + brow) * 68 + bcolw);
        bbase[1] = su(Bsu + (wn * 32 + 16 + brow) * 68 + bcolw);

        float c[2][4][4] = {};
#pragma unroll
        for (int kw = 0; kw < 64; kw += 8) {
            unsigned a[2][4], bb[2][4];
            ldsm4(a[0], abase[0] + kw * 4);
            if (wm < 3) ldsm4(a[1], abase[1] + kw * 4);
            ldsm4(bb[0], bbase[0] + kw * 4);
            ldsm4(bb[1], bbase[1] + kw * 4);
#pragma unroll
            for (int ni = 0; ni < 4; ni++) {
                mma16(c[0][ni], a[0], &bb[ni >> 1][(ni & 1) * 2]);
                if (wm < 3) mma16(c[1][ni], a[1], &bb[ni >> 1][(ni & 1) * 2]);
            }
        }

        const float* bias = (sel == 0) ? bq : (sel == 1) ? bk : bvp;
#pragma unroll
        for (int mi = 0; mi < 2; mi++) {
#pragma unroll
            for (int ni = 0; ni < 4; ni++) {
#pragma unroll
                for (int r2 = 0; r2 < 2; r2++) {
                    int row = wm * 32 + mi * 16 + gr + r2 * 8;
                    if (row >= CC) continue;
                    int col = wn * 32 + ni * 8 + 2 * gc;
                    float v0 = c[mi][ni][2 * r2]     + bias[col];
                    float v1 = c[mi][ni][2 * r2 + 1] + bias[col + 1];
                    if (sel == 0) {
                        qall[row * 68 + (col >> 1)] = packbf(v0, v1);
                    } else if (sel == 1) {
                        kall[row * 68 + (col >> 1)] = packbf(v0, v1);
                    } else {
                        __nv_bfloat16* vth = (__nv_bfloat16*)vt;
                        vth[col * 120 + row]       = __float2bfloat16(v0);
                        vth[(col + 1) * 120 + row] = __float2bfloat16(v1);
                    }
                }
            }
        }
        if (sel < 2) { CP_WAIT0(); __syncthreads(); }
    }
    __syncthreads();   // q/k/v smem visible to all (wo cp.async still in flight)

    // ================= Attention: 56 warp-tasks (8 heads x 7 m-tiles) =======
    const float C = 0.25f * 1.44269504088896f;
    for (int t = warp; t < 56; t += 16) {
        int mt = t >> 3, h = t & 7;

        unsigned a[4];
        ldsm4(a, su(qall + (mt * 16 + arow) * 68 + h * 8 + acolw));
        float s[14][4] = {};
#pragma unroll
        for (int bj = 0; bj < 7; bj++) {
            unsigned bb[4];
            ldsm4(bb, su(kall + (bj * 16 + brow) * 68 + h * 8 + bcolw));
            mma16(s[2 * bj],     a, &bb[0]);
            mma16(s[2 * bj + 1], a, &bb[2]);
        }

        float sum0 = 0.f, sum1 = 0.f;
        unsigned ap[7][4];
#pragma unroll
        for (int kk = 0; kk < 7; kk++) {
            float e00 = ex2(s[2 * kk][0] * C),     e01 = ex2(s[2 * kk][1] * C);
            float e02 = ex2(s[2 * kk][2] * C),     e03 = ex2(s[2 * kk][3] * C);
            float e10 = ex2(s[2 * kk + 1][0] * C), e11 = ex2(s[2 * kk + 1][1] * C);
            float e12 = ex2(s[2 * kk + 1][2] * C), e13 = ex2(s[2 * kk + 1][3] * C);
            sum0 += (e00 + e01) + (e10 + e11);
            sum1 += (e02 + e03) + (e12 + e13);
            ap[kk][0] = packbf(e00, e01);
            ap[kk][1] = packbf(e02, e03);
            ap[kk][2] = packbf(e10, e11);
            ap[kk][3] = packbf(e12, e13);
        }
        sum0 += __shfl_xor_sync(0xFFFFFFFFu, sum0, 1);
        sum0 += __shfl_xor_sync(0xFFFFFFFFu, sum0, 2);
        sum1 += __shfl_xor_sync(0xFFFFFFFFu, sum1, 1);
        sum1 += __shfl_xor_sync(0xFFFFFFFFu, sum1, 2);
        float inv0 = 1.f / sum0, inv1 = 1.f / sum1;

        float o[2][4] = {};
        unsigned bpv = su(vt + (h * 16 + brow) * 60 + bcolw);
#pragma unroll
        for (int kk = 0; kk < 7; kk++) {
            unsigned bb[4];
            ldsm4(bb, bpv + kk * 32);
            mma16(o[0], ap[kk], &bb[0]);
            mma16(o[1], ap[kk], &bb[2]);
        }
#pragma unroll
        for (int ni = 0; ni < 2; ni++) {
            o[ni][0] *= inv0; o[ni][1] *= inv0;
            o[ni][2] *= inv1; o[ni][3] *= inv1;
#pragma unroll
            for (int r2 = 0; r2 < 2; r2++) {
                int sq = mt * 16 + gr + r2 * 8;
                Asu[sq * 68 + h * 8 + ni * 4 + gc] =
                    packbf(o[ni][2 * r2], o[ni][2 * r2 + 1]);
            }
        }
    }
    CP_WAIT0();        // wo landed in B1
    __syncthreads();   // Xs (attn out) visible

    // ================= Output projection =================
    {
        unsigned bbase2[2];
        bbase2[0] = su(B1 + (wn * 32 + brow) * 68 + bcolw);
        bbase2[1] = su(B1 + (wn * 32 + 16 + brow) * 68 + bcolw);

        float c[2][4][4] = {};
#pragma unroll
        for (int kw = 0; kw < 64; kw += 8) {
            unsigned a[2][4], bb[2][4];
            ldsm4(a[0], abase[0] + kw * 4);
            if (wm < 3) ldsm4(a[1], abase[1] + kw * 4);
            ldsm4(bb[0], bbase2[0] + kw * 4);
            ldsm4(bb[1], bbase2[1] + kw * 4);
#pragma unroll
            for (int ni = 0; ni < 4; ni++) {
                mma16(c[0][ni], a[0], &bb[ni >> 1][(ni & 1) * 2]);
                if (wm < 3) mma16(c[1][ni], a[1], &bb[ni >> 1][(ni & 1) * 2]);
            }
        }
        __syncthreads();   // done reading Xs/Ws; ys overlays words [0, 16896)

        float* ys = (float*)smu;
#pragma unroll
        for (int mi = 0; mi < 2; mi++) {
#pragma unroll
            for (int ni = 0; ni < 4; ni++) {
#pragma unroll
                for (int r2 = 0; r2 < 2; r2++) {
                    int row = wm * 32 + mi * 16 + gr + r2 * 8;
                    if (row >= CC) continue;
                    int col = wn * 32 + ni * 8 + 2 * gc;
                    const float* srow = g_src + ((size_t)b * CC + row) * DD;
                    ys[row * 132 + col]     = c[mi][ni][2*r2]   + bo[col]   + srow[col];
                    ys[row * 132 + col + 1] = c[mi][ni][2*r2+1] + bo[col+1] + srow[col+1];
                }
            }
        }
        __syncthreads();

        // LayerNorm: 16 warps x 7 rows
#pragma unroll
        for (int rr = 0; rr < 7; rr++) {
            int r = warp * 7 + rr;
            float4 v4 = *(const float4*)(ys + r * 132 + lane * 4);
            float vals[4] = {v4.x, v4.y, v4.z, v4.w};
            float s1 = vals[0] + vals[1] + vals[2] + vals[3];
            float s2 = vals[0]*vals[0] + vals[1]*vals[1] + vals[2]*vals[2] + vals[3]*vals[3];
#pragma unroll
            for (int off = 16; off > 0; off >>= 1) {
                s1 += __shfl_xor_sync(0xFFFFFFFFu, s1, off);
                s2 += __shfl_xor_sync(0xFFFFFFFFu, s2, off);
            }
            float mu = s1 * (1.f / 128.f);
            float var = s2 * (1.f / 128.f) - mu * mu;
            float inv = rsqrtf(var + 1e-5f);
#pragma unroll
            for (int j = 0; j < 4; j++) {
                int cidx = lane * 4 + j;
                out[((size_t)b * CC + r) * DD + cidx] =
                    (vals[j] - mu) * inv * lg[cidx] + lb[cidx];
            }
        }
    }
}

// ---------------------------------------------------------------------------
extern "C" void kernel_launch(void* const* d_in, const int* in_sizes, int n_in,
                              void* d_out, int out_size) {
    const float* x   = (const float*)d_in[0];
    const float* cw  = (const float*)d_in[1];
    const float* cb  = (const float*)d_in[2];
    const float* bg  = (const float*)d_in[3];
    const float* bb_ = (const float*)d_in[4];
    const float* bm  = (const float*)d_in[5];
    const float* bvv = (const float*)d_in[6];
    const float* wq  = (const float*)d_in[7];
    const float* bq  = (const float*)d_in[8];
    const float* wk  = (const float*)d_in[9];
    const float* bk  = (const float*)d_in[10];
    const float* wv  = (const float*)d_in[11];
    const float* bv  = (const float*)d_in[12];
    const float* wo  = (const float*)d_in[13];
    const float* bo  = (const float*)d_in[14];
    const float* lg  = (const float*)d_in[15];
    const float* lb  = (const float*)d_in[16];
    float* out = (float*)d_out;

    const int FUSED_SMEM = 49024 * 4;   // 196096 B
    cudaFuncSetAttribute(k_fused, cudaFuncAttributeMaxDynamicSharedMemorySize, FUSED_SMEM);

    k_prep<<<64, 256>>>(wq, wk, wv, wo);
    k_conv<<<MM / 8, 256>>>(x, cw, cb, bg, bb_, bm, bvv);
    k_fused<<<BB, NT, FUSED_SMEM>>>(bq, bk, bv, bo, lg, lb, out);
}

// round 8
// speedup vs baseline: 7.5508x; 1.0631x over previous
#include <cuda_runtime.h>
#include <cuda_bf16.h>
#include <cstdint>

#define BB 512
#define CC 112
#define DD 128
#define HH 8
#define HDIM 16
#define KW 8
#define MM (BB*CC)   // 57344
#define NT 512

// Scratch (allocation-free contract)
__device__ float g_src[(size_t)MM * DD];           // fp32 residual
__device__ __nv_bfloat16 g_srcb[(size_t)MM * DD];  // bf16 copy for GEMM A
__device__ __nv_bfloat16 g_wb[4 * DD * DD];        // bf16 wq|wk|wv|wo

__device__ __forceinline__ unsigned packbf(float a, float b) {
    __nv_bfloat162 p = __floats2bfloat162_rn(a, b);
    return *reinterpret_cast<unsigned*>(&p);
}
__device__ __forceinline__ float ex2(float x) {
    float r;
    asm("ex2.approx.f32 %0, %1;" : "=f"(r) : "f"(x));
    return r;
}
__device__ __forceinline__ void mma16(float* c, const unsigned* a, const unsigned* b) {
    asm volatile(
        "mma.sync.aligned.m16n8k16.row.col.f32.bf16.bf16.f32 "
        "{%0,%1,%2,%3}, {%4,%5,%6,%7}, {%8,%9}, {%0,%1,%2,%3};"
        : "+f"(c[0]), "+f"(c[1]), "+f"(c[2]), "+f"(c[3])
        : "r"(a[0]), "r"(a[1]), "r"(a[2]), "r"(a[3]), "r"(b[0]), "r"(b[1]));
}
__device__ __forceinline__ void ldsm4(unsigned* r, unsigned addr) {
    asm volatile("ldmatrix.sync.aligned.m8n8.x4.shared.b16 {%0,%1,%2,%3}, [%4];"
        : "=r"(r[0]), "=r"(r[1]), "=r"(r[2]), "=r"(r[3]) : "r"(addr));
}
__device__ __forceinline__ void stsm2(unsigned addr, unsigned r0, unsigned r1) {
    asm volatile("stmatrix.sync.aligned.m8n8.x2.shared.b16 [%0], {%1,%2};"
        :: "r"(addr), "r"(r0), "r"(r1) : "memory");
}
__device__ __forceinline__ void stsm2t(unsigned addr, unsigned r0, unsigned r1) {
    asm volatile("stmatrix.sync.aligned.m8n8.x2.trans.shared.b16 [%0], {%1,%2};"
        :: "r"(addr), "r"(r0), "r"(r1) : "memory");
}
__device__ __forceinline__ void stsm4(unsigned addr, unsigned r0, unsigned r1,
                                      unsigned r2, unsigned r3) {
    asm volatile("stmatrix.sync.aligned.m8n8.x4.shared.b16 [%0], {%1,%2,%3,%4};"
        :: "r"(addr), "r"(r0), "r"(r1), "r"(r2), "r"(r3) : "memory");
}
__device__ __forceinline__ unsigned su(const void* p) {
    return (unsigned)__cvta_generic_to_shared(p);
}
__device__ __forceinline__ void cpa16(unsigned dst, const void* src) {
    asm volatile("cp.async.cg.shared.global [%0], [%1], 16;" :: "r"(dst), "l"(src));
}
#define CP_COMMIT() asm volatile("cp.async.commit_group;")
#define CP_WAIT0()  asm volatile("cp.async.wait_group 0;")
#define CP_WAIT1()  asm volatile("cp.async.wait_group 1;")

// ---------------------------------------------------------------------------
// Kernel 1: conv -> GELU -> BN -> residual (blocks < MM/8);
//           extra 64 blocks convert weights fp32->bf16 (former k_prep).
// ---------------------------------------------------------------------------
__global__ void __launch_bounds__(256) k_conv(
        const float* __restrict__ x,
        const float* __restrict__ cw, const float* __restrict__ cb,
        const float* __restrict__ bg, const float* __restrict__ bbias,
        const float* __restrict__ bm, const float* __restrict__ bvv,
        const float* __restrict__ wq, const float* __restrict__ wk,
        const float* __restrict__ wv, const float* __restrict__ wo) {
    if (blockIdx.x >= MM / 8) {
        int bid2 = blockIdx.x - MM / 8;       // 0..63
        int m = bid2 >> 4;
        const float* s = (m == 0) ? wq : (m == 1) ? wk : (m == 2) ? wv : wo;
        int i = ((bid2 & 15) * 256 + threadIdx.x) * 4;
        float4 v = *(const float4*)(s + i);
        uint2 p = {packbf(v.x, v.y), packbf(v.z, v.w)};
        *(uint2*)(g_wb + m * DD * DD + i) = p;
        return;
    }
    __shared__ float xs[8 * DD];
    int tid = threadIdx.x;
    int row = tid >> 5, col = (tid & 31) * 4;
    int gr = blockIdx.x * 8 + row;
    float4 v = *(const float4*)(x + (size_t)gr * DD + col);
    *(float4*)&xs[row * DD + col] = v;
    __syncthreads();

    int c = gr % CC;
    float w[KW];
#pragma unroll
    for (int k = 0; k < KW; k++) w[k] = cw[c * KW + k];
    float bias = cb[c];
    float bnsc = bg[c] * rsqrtf(bvv[c] + 1e-5f);
    float bnm = bm[c], bnb = bbias[c];

    float so[4];
#pragma unroll
    for (int j = 0; j < 4; j++) {
        int d = col + j;
        float acc = 0.f;
#pragma unroll
        for (int k = 0; k < KW; k++) {
            int idx = d - 3 + k;
            float xv = (idx >= 0 && idx < DD) ? xs[row * DD + idx] : 0.f;
            acc += xv * w[k];
        }
        acc += bias;
        float g = 0.5f * acc * (1.f + erff(acc * 0.70710678118654752f));
        float h = (g - bnm) * bnsc + bnb;
        so[j] = xs[row * DD + d] + h;
    }
    *(float4*)(g_src + (size_t)gr * DD + col) = make_float4(so[0], so[1], so[2], so[3]);
    uint2 p = {packbf(so[0], so[1]), packbf(so[2], so[3])};
    *(uint2*)(g_srcb + (size_t)gr * DD + col) = p;
}

// ---------------------------------------------------------------------------
// Kernel 2 (MEGAFUSED): per-batch block: QKV GEMM -> 8-head attention ->
// output projection -> residual -> LayerNorm. 512 threads, 196KB smem.
// smem word map:
//   [0     , 8704 )  Asu  : src A [128][68]; attn-out overlay; ys (w/ B0)
//   [8704  , 17408)  B0   : weight buf [128][68]
//   [17408 , 26112)  B1   : weight buf [128][68]
//   [26112 , 33728)  qall : Q [112][68];  later fp32-src prefetch (w/ kall)
//   [33728 , 41344)  kall : K [112][68]
//   [41344 , 49024)  vt   : V^T [128][60w]
// ---------------------------------------------------------------------------
__global__ void __launch_bounds__(NT) k_fused(
        const float* __restrict__ bq, const float* __restrict__ bk,
        const float* __restrict__ bvp, const float* __restrict__ bo,
        const float* __restrict__ lg, const float* __restrict__ lb,
        float* __restrict__ out) {
    extern __shared__ unsigned smu[];
    unsigned* Asu  = smu;
    unsigned* B0   = smu + 8704;
    unsigned* B1   = smu + 17408;
    unsigned* qall = smu + 26112;
    unsigned* kall = smu + 33728;
    unsigned* vt   = smu + 41344;

    int tid = threadIdx.x;
    int b = blockIdx.x;
    int lane = tid & 31, warp = tid >> 5;
    int wm = warp >> 2, wn = warp & 3;
    int gr = lane >> 2, gc = lane & 3;

    int arow = (lane & 7) + ((lane >> 3) & 1) * 8;
    int acolw = (lane >> 4) * 4;
    int brow = (lane & 7) + ((lane >> 4) & 1) * 8;
    int bcolw = ((lane >> 3) & 1) * 4;

    // ---- stage A (112 src rows bf16) + zero pad + B0 = wq
    const char* ag = (const char*)g_srcb + (size_t)b * CC * 256;
#pragma unroll
    for (int i = tid; i < 1792; i += NT) {
        int row = i >> 4, q4 = i & 15;
        cpa16(su(Asu + row * 68 + q4 * 4), ag + i * 16);
    }
#pragma unroll
    for (int i = tid; i < 1088; i += NT) Asu[112 * 68 + i] = 0;
    {
        const char* wg = (const char*)g_wb;
#pragma unroll
        for (int i = tid; i < 2048; i += NT) {
            int row = i >> 4, q4 = i & 15;
            cpa16(su(B0 + row * 68 + q4 * 4), wg + i * 16);
        }
    }
    CP_COMMIT(); CP_WAIT0();
    __syncthreads();

    unsigned abase[2];
    abase[0] = su(Asu + (wm * 32 + arow) * 68 + acolw);
    abase[1] = su(Asu + (wm * 32 + 16 + arow) * 68 + acolw);

    // ================= QKV GEMMs =================
    for (int sel = 0; sel < 3; sel++) {
        {   // prefetch next weight matrix (wk, wv, then wo)
            const char* nw = (const char*)g_wb + (size_t)((sel < 2) ? sel + 1 : 3) * 32768;
            unsigned* dstb = (sel == 1) ? B0 : B1;
#pragma unroll
            for (int i = tid; i < 2048; i += NT) {
                int row = i >> 4, q4 = i & 15;
                cpa16(su(dstb + row * 68 + q4 * 4), nw + i * 16);
            }
            CP_COMMIT();
        }
        unsigned* Bsu = (sel & 1) ? B1 : B0;
        unsigned bbase[2];
        bbase[0] = su(Bsu + (wn * 32 + brow) * 68 + bcolw);
        bbase[1] = su(Bsu + (wn * 32 + 16 + brow) * 68 + bcolw);

        float c[2][4][4] = {};
#pragma unroll
        for (int kw = 0; kw < 64; kw += 8) {
            unsigned a[2][4], bb[2][4];
            ldsm4(a[0], abase[0] + kw * 4);
            if (wm < 3) ldsm4(a[1], abase[1] + kw * 4);
            ldsm4(bb[0], bbase[0] + kw * 4);
            ldsm4(bb[1], bbase[1] + kw * 4);
#pragma unroll
            for (int ni = 0; ni < 4; ni++) {
                mma16(c[0][ni], a[0], &bb[ni >> 1][(ni & 1) * 2]);
                if (wm < 3) mma16(c[1][ni], a[1], &bb[ni >> 1][(ni & 1) * 2]);
            }
        }

        const float* bias = (sel == 0) ? bq : (sel == 1) ? bk : bvp;
#pragma unroll
        for (int mi = 0; mi < 2; mi++) {
            if (wm == 3 && mi == 1) continue;   // rows 112..127 are padding
            int R0 = wm * 32 + mi * 16;
#pragma unroll
            for (int ni = 0; ni < 4; ni++) {
                int C0 = wn * 32 + ni * 8;
                int col = C0 + 2 * gc;
                float v00 = c[mi][ni][0] + bias[col];
                float v01 = c[mi][ni][1] + bias[col + 1];
                float v10 = c[mi][ni][2] + bias[col];
                float v11 = c[mi][ni][3] + bias[col + 1];
                unsigned p0 = packbf(v00, v01), p1 = packbf(v10, v11);
                if (sel == 0) {
                    unsigned ad = su(qall) + 4 * ((R0 + (lane & 15)) * 68 + (C0 >> 1));
                    stsm2(ad, p0, p1);
                } else if (sel == 1) {
                    unsigned ad = su(kall) + 4 * ((R0 + (lane & 15)) * 68 + (C0 >> 1));
                    stsm2(ad, p0, p1);
                } else {
                    // V transposed: vth[col][row], row stride 240B
                    unsigned ad = su(vt) + (C0 + (lane & 7)) * 240 + (R0 + (lane & 8)) * 2;
                    stsm2t(ad, p0, p1);
                }
            }
        }
        if (sel < 2) { CP_WAIT0(); __syncthreads(); }
    }
    __syncthreads();   // q/k/vt visible (wo cp.async still in flight)

    // ================= Attention: 56 warp-tasks (8 heads x 7 m-tiles) =======
    const float C = 0.25f * 1.44269504088896f;
    for (int t = warp; t < 56; t += 16) {
        int mt = t >> 3, h = t & 7;

        unsigned a[4];
        ldsm4(a, su(qall + (mt * 16 + arow) * 68 + h * 8 + acolw));
        float s[14][4] = {};
#pragma unroll
        for (int bj = 0; bj < 7; bj++) {
            unsigned bb[4];
            ldsm4(bb, su(kall + (bj * 16 + brow) * 68 + h * 8 + bcolw));
            mma16(s[2 * bj],     a, &bb[0]);
            mma16(s[2 * bj + 1], a, &bb[2]);
        }

        float sum0 = 0.f, sum1 = 0.f;
        unsigned ap[7][4];
#pragma unroll
        for (int kk = 0; kk < 7; kk++) {
            float e00 = ex2(s[2 * kk][0] * C),     e01 = ex2(s[2 * kk][1] * C);
            float e02 = ex2(s[2 * kk][2] * C),     e03 = ex2(s[2 * kk][3] * C);
            float e10 = ex2(s[2 * kk + 1][0] * C), e11 = ex2(s[2 * kk + 1][1] * C);
            float e12 = ex2(s[2 * kk + 1][2] * C), e13 = ex2(s[2 * kk + 1][3] * C);
            sum0 += (e00 + e01) + (e10 + e11);
            sum1 += (e02 + e03) + (e12 + e13);
            ap[kk][0] = packbf(e00, e01);
            ap[kk][1] = packbf(e02, e03);
            ap[kk][2] = packbf(e10, e11);
            ap[kk][3] = packbf(e12, e13);
        }
        sum0 += __shfl_xor_sync(0xFFFFFFFFu, sum0, 1);
        sum0 += __shfl_xor_sync(0xFFFFFFFFu, sum0, 2);
        sum1 += __shfl_xor_sync(0xFFFFFFFFu, sum1, 1);
        sum1 += __shfl_xor_sync(0xFFFFFFFFu, sum1, 2);
        float inv0 = 1.f / sum0, inv1 = 1.f / sum1;

        float o[2][4] = {};
        unsigned bpv = su(vt + (h * 16 + brow) * 60 + bcolw);
#pragma unroll
        for (int kk = 0; kk < 7; kk++) {
            unsigned bb[4];
            ldsm4(bb, bpv + kk * 32);
            mma16(o[0], ap[kk], &bb[0]);
            mma16(o[1], ap[kk], &bb[2]);
        }
        o[0][0] *= inv0; o[0][1] *= inv0; o[0][2] *= inv1; o[0][3] *= inv1;
        o[1][0] *= inv0; o[1][1] *= inv0; o[1][2] *= inv1; o[1][3] *= inv1;
        // attn out 16x16 tile -> Asu via stmatrix.x4
        int R0 = mt * 16, C0 = h * 16;
        unsigned ad = su(Asu) + 4 * ((R0 + (lane & 15)) * 68 + (C0 >> 1) + (lane >> 4) * 4);
        stsm4(ad, packbf(o[0][0], o[0][1]), packbf(o[0][2], o[0][3]),
                  packbf(o[1][0], o[1][1]), packbf(o[1][2], o[1][3]));
    }
    __syncthreads();   // attn out visible; qall/kall dead

    // prefetch fp32 src (residual) into qall+kall region; hidden by outproj GEMM
    {
        const char* sg = (const char*)(g_src + (size_t)b * CC * DD);
#pragma unroll
        for (int i = tid; i < 3584; i += NT)
            cpa16(su(qall + i * 4), sg + i * 16);
        CP_COMMIT();
    }
    CP_WAIT1();        // wo resident in B1 (src group may still be pending)

    // ================= Output projection =================
    {
        unsigned bbase2[2];
        bbase2[0] = su(B1 + (wn * 32 + brow) * 68 + bcolw);
        bbase2[1] = su(B1 + (wn * 32 + 16 + brow) * 68 + bcolw);

        float c[2][4][4] = {};
#pragma unroll
        for (int kw = 0; kw < 64; kw += 8) {
            unsigned a[2][4], bb[2][4];
            ldsm4(a[0], abase[0] + kw * 4);
            if (wm < 3) ldsm4(a[1], abase[1] + kw * 4);
            ldsm4(bb[0], bbase2[0] + kw * 4);
            ldsm4(bb[1], bbase2[1] + kw * 4);
#pragma unroll
            for (int ni = 0; ni < 4; ni++) {
                mma16(c[0][ni], a[0], &bb[ni >> 1][(ni & 1) * 2]);
                if (wm < 3) mma16(c[1][ni], a[1], &bb[ni >> 1][(ni & 1) * 2]);
            }
        }
        CP_WAIT0();        // src fp32 resident
        __syncthreads();   // done reading Asu/B1; ys overlays words [0,16896)

        float* ys = (float*)smu;
        const float* ssm = (const float*)qall;   // fp32 src [112][128]
#pragma unroll
        for (int mi = 0; mi < 2; mi++) {
#pragma unroll
            for (int ni = 0; ni < 4; ni++) {
#pragma unroll
                for (int r2 = 0; r2 < 2; r2++) {
                    int row = wm * 32 + mi * 16 + gr + r2 * 8;
                    if (row >= CC) continue;
                    int col = wn * 32 + ni * 8 + 2 * gc;
                    float2 s2 = *(const float2*)(ssm + row * DD + col);
                    ys[row * 132 + col]     = c[mi][ni][2*r2]   + bo[col]   + s2.x;
                    ys[row * 132 + col + 1] = c[mi][ni][2*r2+1] + bo[col+1] + s2.y;
                }
            }
        }
        __syncthreads();

        // LayerNorm: 16 warps x 7 rows
#pragma unroll
        for (int rr = 0; rr < 7; rr++) {
            int r = warp * 7 + rr;
            float4 v4 = *(const float4*)(ys + r * 132 + lane * 4);
            float vals[4] = {v4.x, v4.y, v4.z, v4.w};
            float s1 = vals[0] + vals[1] + vals[2] + vals[3];
            float s2 = vals[0]*vals[0] + vals[1]*vals[1] + vals[2]*vals[2] + vals[3]*vals[3];
#pragma unroll
            for (int off = 16; off > 0; off >>= 1) {
                s1 += __shfl_xor_sync(0xFFFFFFFFu, s1, off);
                s2 += __shfl_xor_sync(0xFFFFFFFFu, s2, off);
            }
            float mu = s1 * (1.f / 128.f);
            float var = s2 * (1.f / 128.f) - mu * mu;
            float inv = rsqrtf(var + 1e-5f);
#pragma unroll
            for (int j = 0; j < 4; j++) {
                int cidx = lane * 4 + j;
                out[((size_t)b * CC + r) * DD + cidx] =
                    (vals[j] - mu) * inv * lg[cidx] + lb[cidx];
            }
        }
    }
}

// ---------------------------------------------------------------------------
extern "C" void kernel_launch(void* const* d_in, const int* in_sizes, int n_in,
                              void* d_out, int out_size) {
    const float* x   = (const float*)d_in[0];
    const float* cw  = (const float*)d_in[1];
    const float* cb  = (const float*)d_in[2];
    const float* bg  = (const float*)d_in[3];
    const float* bb_ = (const float*)d_in[4];
    const float* bm  = (const float*)d_in[5];
    const float* bvv = (const float*)d_in[6];
    const float* wq  = (const float*)d_in[7];
    const float* bq  = (const float*)d_in[8];
    const float* wk  = (const float*)d_in[9];
    const float* bk  = (const float*)d_in[10];
    const float* wv  = (const float*)d_in[11];
    const float* bv  = (const float*)d_in[12];
    const float* wo  = (const float*)d_in[13];
    const float* bo  = (const float*)d_in[14];
    const float* lg  = (const float*)d_in[15];
    const float* lb  = (const float*)d_in[16];
    float* out = (float*)d_out;

    const int FUSED_SMEM = 49024 * 4;   // 196096 B
    cudaFuncSetAttribute(k_fused, cudaFuncAttributeMaxDynamicSharedMemorySize, FUSED_SMEM);

    k_conv<<<MM / 8 + 64, 256>>>(x, cw, cb, bg, bb_, bm, bvv, wq, wk, wv, wo);
    k_fused<<<BB, NT, FUSED_SMEM>>>(bq, bk, bv, bo, lg, lb, out);
}